// round 4
// baseline (speedup 1.0000x reference)
#include <cuda_runtime.h>
#include <math.h>

#define N_TOK 1024
#define CQ    768
#define CZ    128
#define NH    16
#define HD    48
#define HDM   (NH*HD)              // 768
#define NN    ((size_t)N_TOK*(size_t)N_TOK)

// ---------------- scratch (device globals: no allocation allowed) ----------
__device__ float d_an[N_TOK*CQ];                    // LayerNorm(a)
__device__ float d_qkvg[(size_t)N_TOK*4*HDM];       // [tok][q|k|v|g] cols 0..3071
__device__ float d_pb[16ULL*1024ULL*1024ULL];       // pair bias -> scores -> probs
__device__ float d_og[N_TOK*HDM];                   // gated attention output

// ---------------- f32x2 packed FMA (Blackwell FFMA2, PTX-only) -------------
__device__ __forceinline__ float2 ffma2(float2 a, float2 b, float2 c) {
    float2 d;
    asm("fma.rn.f32x2 %0, %1, %2, %3;"
        : "=l"(reinterpret_cast<unsigned long long&>(d))
        : "l"(reinterpret_cast<unsigned long long&>(a)),
          "l"(reinterpret_cast<unsigned long long&>(b)),
          "l"(reinterpret_cast<unsigned long long&>(c)));
    return d;
}
__device__ __forceinline__ float2 f2b(float x) { return make_float2(x, x); }

// ---------------- 1) LayerNorm over a: [1024][768] -------------------------
__global__ void ln_a_kernel(const float* __restrict__ a, const float* __restrict__ g,
                            const float* __restrict__ b) {
    int row = blockIdx.x, tid = threadIdx.x;
    const float* x = a + (size_t)row * CQ;
    float v0 = x[tid], v1 = x[tid + 256], v2 = x[tid + 512];
    float s = v0 + v1 + v2;
    float s2 = v0 * v0 + v1 * v1 + v2 * v2;
#pragma unroll
    for (int o = 16; o; o >>= 1) {
        s  += __shfl_xor_sync(0xffffffffu, s, o);
        s2 += __shfl_xor_sync(0xffffffffu, s2, o);
    }
    __shared__ float rs[8], rs2[8], bc[2];
    int w = tid >> 5;
    if ((tid & 31) == 0) { rs[w] = s; rs2[w] = s2; }
    __syncthreads();
    if (tid == 0) {
        float S = 0.f, S2 = 0.f;
        for (int i = 0; i < 8; i++) { S += rs[i]; S2 += rs2[i]; }
        float mu = S * (1.f / 768.f);
        float var = S2 * (1.f / 768.f) - mu * mu;
        bc[0] = mu; bc[1] = rsqrtf(var + 1e-5f);
    }
    __syncthreads();
    float mu = bc[0], rstd = bc[1];
    float* o = d_an + (size_t)row * CQ;
    o[tid]       = (v0 - mu) * rstd * g[tid]       + b[tid];
    o[tid + 256] = (v1 - mu) * rstd * g[tid + 256] + b[tid + 256];
    o[tid + 512] = (v2 - mu) * rstd * g[tid + 512] + b[tid + 512];
}

// ---------------- 2) SGEMM 64x64 tiles, f32x2 micro 4x4 --------------------
// C[m][n] = sum_k A[m][k] * W[k][n]; modes: 0 none, 1 *scale, 2 sigmoid(x+bias), 3 +bias
__global__ void sgemm64(const float* __restrict__ A, const float* __restrict__ W,
                        float* __restrict__ C, int K, int N, int ldc,
                        int mode, const float* __restrict__ bias, float scale) {
    __shared__ float As[16][68];
    __shared__ float Bs[16][64];
    int tid = threadIdx.x;
    int m_blk = blockIdx.y * 64, n_blk = blockIdx.x * 64;
    int tx = tid & 15, ty = tid >> 4;
    int ar = tid >> 2, ac4 = tid & 3;
    int br = tid >> 4, bc4 = tid & 15;
    const float* Ap = A + (size_t)(m_blk + ar) * K + ac4 * 4;
    const float* Wp = W + (size_t)br * N + n_blk + bc4 * 4;
    float2 acc[4][2];
#pragma unroll
    for (int i = 0; i < 4; i++) { acc[i][0] = make_float2(0.f, 0.f); acc[i][1] = make_float2(0.f, 0.f); }

    for (int k0 = 0; k0 < K; k0 += 16) {
        float4 av = *(const float4*)(Ap + k0);
        float4 bv = *(const float4*)(Wp + (size_t)k0 * N);
        __syncthreads();
        As[ac4 * 4 + 0][ar] = av.x; As[ac4 * 4 + 1][ar] = av.y;
        As[ac4 * 4 + 2][ar] = av.z; As[ac4 * 4 + 3][ar] = av.w;
        *(float4*)&Bs[br][bc4 * 4] = bv;
        __syncthreads();
#pragma unroll
        for (int kk = 0; kk < 16; ++kk) {
            float4 a4 = *(const float4*)&As[kk][ty * 4];
            float4 b4 = *(const float4*)&Bs[kk][tx * 4];
            float2 b01 = make_float2(b4.x, b4.y), b23 = make_float2(b4.z, b4.w);
            acc[0][0] = ffma2(f2b(a4.x), b01, acc[0][0]); acc[0][1] = ffma2(f2b(a4.x), b23, acc[0][1]);
            acc[1][0] = ffma2(f2b(a4.y), b01, acc[1][0]); acc[1][1] = ffma2(f2b(a4.y), b23, acc[1][1]);
            acc[2][0] = ffma2(f2b(a4.z), b01, acc[2][0]); acc[2][1] = ffma2(f2b(a4.z), b23, acc[2][1]);
            acc[3][0] = ffma2(f2b(a4.w), b01, acc[3][0]); acc[3][1] = ffma2(f2b(a4.w), b23, acc[3][1]);
        }
    }
#pragma unroll
    for (int i = 0; i < 4; i++) {
        int m = m_blk + ty * 4 + i;
        float vals[4] = { acc[i][0].x, acc[i][0].y, acc[i][1].x, acc[i][1].y };
        float4 o;
#pragma unroll
        for (int jn = 0; jn < 4; jn++) {
            int n = n_blk + tx * 4 + jn;
            float v = vals[jn];
            if (mode == 1) v *= scale;
            else if (mode == 2) v = 1.f / (1.f + __expf(-(v + bias[n])));
            else if (mode == 3) v += bias[n];
            ((float*)&o)[jn] = v;
        }
        *(float4*)(C + (size_t)m * ldc + n_blk + tx * 4) = o;
    }
}

// ---------------- 3) pair bias: fused LN(z) + zn@w_z + mask bias -----------
// block: fixed i, 32 j rows. pb[h][i][j]
__global__ void pair_bias_kernel(const float* __restrict__ z, const float* __restrict__ gz,
                                 const float* __restrict__ bz, const float* __restrict__ wz,
                                 const float* __restrict__ mask) {
    __shared__ float zs[32][132];   // normalized z rows, padded
    __shared__ float2 wt[8][128];   // w_z transposed, head-pair packed
    int i = blockIdx.y;
    int j0 = blockIdx.x * 32;
    int tid = threadIdx.x;
    for (int idx = tid; idx < 1024; idx += 256) {
        int c = idx & 127, hp = idx >> 7;
        wt[hp][c] = make_float2(wz[c * 16 + 2 * hp], wz[c * 16 + 2 * hp + 1]);
    }
    int warp = tid >> 5, lane = tid & 31;
    float4 gq = *(const float4*)(gz + lane * 4);
    float4 bq = *(const float4*)(bz + lane * 4);
#pragma unroll
    for (int rr = 0; rr < 4; ++rr) {
        int r = warp * 4 + rr;
        const float4 v = *(const float4*)(z + ((size_t)i * N_TOK + (j0 + r)) * CZ + lane * 4);
        float s  = v.x + v.y + v.z + v.w;
        float s2 = v.x * v.x + v.y * v.y + v.z * v.z + v.w * v.w;
#pragma unroll
        for (int o = 16; o; o >>= 1) {
            s  += __shfl_xor_sync(0xffffffffu, s, o);
            s2 += __shfl_xor_sync(0xffffffffu, s2, o);
        }
        float mu = s * (1.f / 128.f);
        float var = s2 * (1.f / 128.f) - mu * mu;
        float rstd = rsqrtf(var + 1e-5f);
        float4 o4;
        o4.x = (v.x - mu) * rstd * gq.x + bq.x;
        o4.y = (v.y - mu) * rstd * gq.y + bq.y;
        o4.z = (v.z - mu) * rstd * gq.z + bq.z;
        o4.w = (v.w - mu) * rstd * gq.w + bq.w;
        *(float4*)&zs[r][lane * 4] = o4;
    }
    __syncthreads();
    int jj = warp * 4 + (lane & 3);
    int hp = lane >> 2;
    float2 acc = make_float2(0.f, 0.f);
#pragma unroll
    for (int c = 0; c < 128; c += 4) {
        float4 zq = *(const float4*)&zs[jj][c];
        acc = ffma2(f2b(zq.x), wt[hp][c],     acc);
        acc = ffma2(f2b(zq.y), wt[hp][c + 1], acc);
        acc = ffma2(f2b(zq.z), wt[hp][c + 2], acc);
        acc = ffma2(f2b(zq.w), wt[hp][c + 3], acc);
    }
    int j = j0 + jj;
    float mb = 1.0e9f * (mask[i] * mask[j] - 1.0f);
    size_t base = (size_t)i * N_TOK + j;
    d_pb[(size_t)(2 * hp) * NN + base]     = acc.x + mb;
    d_pb[(size_t)(2 * hp + 1) * NN + base] = acc.y + mb;
}

// ---------------- 4a) scores += q . k  (RMW into pb) -----------------------
__global__ void scores_kernel() {
    __shared__ float qs[48][32];
    __shared__ float ks[48][64];
    int h = blockIdx.z, q0 = blockIdx.y * 32, k0 = blockIdx.x * 64;
    int tid = threadIdx.x;
    for (int idx = tid; idx < 32 * 12; idx += 256) {
        int r = idx / 12, c4 = idx % 12;
        float4 v = *(const float4*)(d_qkvg + (size_t)(q0 + r) * 3072 + h * 48 + c4 * 4);
        qs[c4 * 4 + 0][r] = v.x; qs[c4 * 4 + 1][r] = v.y;
        qs[c4 * 4 + 2][r] = v.z; qs[c4 * 4 + 3][r] = v.w;
    }
    for (int idx = tid; idx < 64 * 12; idx += 256) {
        int r = idx / 12, c4 = idx % 12;
        float4 v = *(const float4*)(d_qkvg + (size_t)(k0 + r) * 3072 + 768 + h * 48 + c4 * 4);
        ks[c4 * 4 + 0][r] = v.x; ks[c4 * 4 + 1][r] = v.y;
        ks[c4 * 4 + 2][r] = v.z; ks[c4 * 4 + 3][r] = v.w;
    }
    __syncthreads();
    int qa = (tid >> 4) * 2, ka = (tid & 15) * 4;
    float2 a00 = make_float2(0.f, 0.f), a01 = a00, a10 = a00, a11 = a00;
#pragma unroll
    for (int d = 0; d < 48; ++d) {
        float2 qv = *(const float2*)&qs[d][qa];
        float4 kv = *(const float4*)&ks[d][ka];
        float2 k01 = make_float2(kv.x, kv.y), k23 = make_float2(kv.z, kv.w);
        a00 = ffma2(f2b(qv.x), k01, a00);
        a01 = ffma2(f2b(qv.x), k23, a01);
        a10 = ffma2(f2b(qv.y), k01, a10);
        a11 = ffma2(f2b(qv.y), k23, a11);
    }
    size_t base = (size_t)h * NN + (size_t)(q0 + qa) * N_TOK + k0 + ka;
    float4 o0 = *(float4*)(d_pb + base);
    o0.x += a00.x; o0.y += a00.y; o0.z += a01.x; o0.w += a01.y;
    *(float4*)(d_pb + base) = o0;
    float4 o1 = *(float4*)(d_pb + base + N_TOK);
    o1.x += a10.x; o1.y += a10.y; o1.z += a11.x; o1.w += a11.y;
    *(float4*)(d_pb + base + N_TOK) = o1;
}

// ---------------- 4b) softmax over k (rows of 1024) ------------------------
__global__ void softmax_kernel() {
    __shared__ float rs[8];
    __shared__ float bcast;
    size_t row = blockIdx.x;
    float* p = d_pb + row * N_TOK;
    int tid = threadIdx.x, w = tid >> 5, lane = tid & 31;
    float4 x = *(float4*)(p + tid * 4);
    float m = fmaxf(fmaxf(x.x, x.y), fmaxf(x.z, x.w));
#pragma unroll
    for (int o = 16; o; o >>= 1) m = fmaxf(m, __shfl_xor_sync(0xffffffffu, m, o));
    if (lane == 0) rs[w] = m;
    __syncthreads();
    if (tid == 0) {
        float M = rs[0];
        for (int i = 1; i < 8; i++) M = fmaxf(M, rs[i]);
        bcast = M;
    }
    __syncthreads();
    float M = bcast;
    float4 e;
    e.x = __expf(x.x - M); e.y = __expf(x.y - M);
    e.z = __expf(x.z - M); e.w = __expf(x.w - M);
    float s = e.x + e.y + e.z + e.w;
#pragma unroll
    for (int o = 16; o; o >>= 1) s += __shfl_xor_sync(0xffffffffu, s, o);
    __syncthreads();
    if (lane == 0) rs[w] = s;
    __syncthreads();
    if (tid == 0) {
        float S = 0.f;
        for (int i = 0; i < 8; i++) S += rs[i];
        bcast = 1.f / S;
    }
    __syncthreads();
    float inv = bcast;
    e.x *= inv; e.y *= inv; e.z *= inv; e.w *= inv;
    *(float4*)(p + tid * 4) = e;
}

// ---------------- 4c) o = p @ v, gated ------------------------------------
__global__ void pv_kernel() {
    __shared__ float ps[32][68];
    __shared__ float vs[64][48];
    int q0 = blockIdx.x * 32, h = blockIdx.y;
    int tid = threadIdx.x;
    int q = tid >> 3, dg = tid & 7, d0 = dg * 6;
    float2 a01 = make_float2(0.f, 0.f), a23 = a01, a45 = a01;
    for (int k0 = 0; k0 < N_TOK; k0 += 64) {
        __syncthreads();
        for (int idx = tid; idx < 32 * 16; idx += 256) {
            int r = idx / 16, c4 = idx % 16;
            *(float4*)&ps[r][c4 * 4] =
                *(const float4*)(d_pb + (size_t)h * NN + (size_t)(q0 + r) * N_TOK + k0 + c4 * 4);
        }
        for (int idx = tid; idx < 64 * 12; idx += 256) {
            int r = idx / 12, c4 = idx % 12;
            *(float4*)&vs[r][c4 * 4] =
                *(const float4*)(d_qkvg + (size_t)(k0 + r) * 3072 + 1536 + h * 48 + c4 * 4);
        }
        __syncthreads();
#pragma unroll 16
        for (int kk = 0; kk < 64; ++kk) {
            float pv = ps[q][kk];
            float2 v01 = *(const float2*)&vs[kk][d0];
            float2 v23 = *(const float2*)&vs[kk][d0 + 2];
            float2 v45 = *(const float2*)&vs[kk][d0 + 4];
            float2 pp = f2b(pv);
            a01 = ffma2(pp, v01, a01);
            a23 = ffma2(pp, v23, a23);
            a45 = ffma2(pp, v45, a45);
        }
    }
    int qr = q0 + q;
    const float* gp = d_qkvg + (size_t)qr * 3072 + 2304 + h * 48 + d0;
    float* op = d_og + (size_t)qr * HDM + h * 48 + d0;
    op[0] = a01.x * gp[0]; op[1] = a01.y * gp[1];
    op[2] = a23.x * gp[2]; op[3] = a23.y * gp[3];
    op[4] = a45.x * gp[4]; op[5] = a45.y * gp[5];
}

// ---------------- thin wrappers needing scratch as A operand ----------------
__global__ void sgemm64_from_an(const float* __restrict__ W, float* __restrict__ C,
                                int colofs, int mode, const float* __restrict__ bias,
                                float scale);

// Use generic sgemm64 via device-global pointers: small trampoline kernels are
// avoided by passing the scratch address through a __device__ pointer read on
// device is overkill — instead we simply give sgemm64 the global directly.
// (d_an/d_og/d_qkvg have fixed addresses at module load; taking their address
// in host code requires cudaGetSymbolAddress, which we avoid. So we wrap:)

__global__ void proj_kernel(const float* __restrict__ W, int dstofs,
                            int mode, const float* __restrict__ bias, float scale) {
    // identical to sgemm64 but A = d_an (K=768), C = d_qkvg (ldc=3072)
    __shared__ float As[16][68];
    __shared__ float Bs[16][64];
    const int K = CQ, N = HDM, ldc = 4 * HDM;
    int tid = threadIdx.x;
    int m_blk = blockIdx.y * 64, n_blk = blockIdx.x * 64;
    int tx = tid & 15, ty = tid >> 4;
    int ar = tid >> 2, ac4 = tid & 3;
    int br = tid >> 4, bc4 = tid & 15;
    const float* Ap = d_an + (size_t)(m_blk + ar) * K + ac4 * 4;
    const float* Wp = W + (size_t)br * N + n_blk + bc4 * 4;
    float2 acc[4][2];
#pragma unroll
    for (int i = 0; i < 4; i++) { acc[i][0] = make_float2(0.f, 0.f); acc[i][1] = make_float2(0.f, 0.f); }
    for (int k0 = 0; k0 < K; k0 += 16) {
        float4 av = *(const float4*)(Ap + k0);
        float4 bv = *(const float4*)(Wp + (size_t)k0 * N);
        __syncthreads();
        As[ac4 * 4 + 0][ar] = av.x; As[ac4 * 4 + 1][ar] = av.y;
        As[ac4 * 4 + 2][ar] = av.z; As[ac4 * 4 + 3][ar] = av.w;
        *(float4*)&Bs[br][bc4 * 4] = bv;
        __syncthreads();
#pragma unroll
        for (int kk = 0; kk < 16; ++kk) {
            float4 a4 = *(const float4*)&As[kk][ty * 4];
            float4 b4 = *(const float4*)&Bs[kk][tx * 4];
            float2 b01 = make_float2(b4.x, b4.y), b23 = make_float2(b4.z, b4.w);
            acc[0][0] = ffma2(f2b(a4.x), b01, acc[0][0]); acc[0][1] = ffma2(f2b(a4.x), b23, acc[0][1]);
            acc[1][0] = ffma2(f2b(a4.y), b01, acc[1][0]); acc[1][1] = ffma2(f2b(a4.y), b23, acc[1][1]);
            acc[2][0] = ffma2(f2b(a4.z), b01, acc[2][0]); acc[2][1] = ffma2(f2b(a4.z), b23, acc[2][1]);
            acc[3][0] = ffma2(f2b(a4.w), b01, acc[3][0]); acc[3][1] = ffma2(f2b(a4.w), b23, acc[3][1]);
        }
    }
#pragma unroll
    for (int i = 0; i < 4; i++) {
        int m = m_blk + ty * 4 + i;
        float vals[4] = { acc[i][0].x, acc[i][0].y, acc[i][1].x, acc[i][1].y };
        float4 o;
#pragma unroll
        for (int jn = 0; jn < 4; jn++) {
            int n = n_blk + tx * 4 + jn;
            float v = vals[jn];
            if (mode == 1) v *= scale;
            else if (mode == 2) v = 1.f / (1.f + __expf(-(v + bias[n])));
            ((float*)&o)[jn] = v;
        }
        *(float4*)(d_qkvg + (size_t)m * ldc + dstofs + n_blk + tx * 4) = o;
    }
}

__global__ void out_proj_kernel(const float* __restrict__ W, const float* __restrict__ bias,
                                float* __restrict__ C) {
    // A = d_og [1024][768], C = out [1024][768] (+bias)
    __shared__ float As[16][68];
    __shared__ float Bs[16][64];
    const int K = HDM, N = CQ, ldc = CQ;
    int tid = threadIdx.x;
    int m_blk = blockIdx.y * 64, n_blk = blockIdx.x * 64;
    int tx = tid & 15, ty = tid >> 4;
    int ar = tid >> 2, ac4 = tid & 3;
    int br = tid >> 4, bc4 = tid & 15;
    const float* Ap = d_og + (size_t)(m_blk + ar) * K + ac4 * 4;
    const float* Wp = W + (size_t)br * N + n_blk + bc4 * 4;
    float2 acc[4][2];
#pragma unroll
    for (int i = 0; i < 4; i++) { acc[i][0] = make_float2(0.f, 0.f); acc[i][1] = make_float2(0.f, 0.f); }
    for (int k0 = 0; k0 < K; k0 += 16) {
        float4 av = *(const float4*)(Ap + k0);
        float4 bv = *(const float4*)(Wp + (size_t)k0 * N);
        __syncthreads();
        As[ac4 * 4 + 0][ar] = av.x; As[ac4 * 4 + 1][ar] = av.y;
        As[ac4 * 4 + 2][ar] = av.z; As[ac4 * 4 + 3][ar] = av.w;
        *(float4*)&Bs[br][bc4 * 4] = bv;
        __syncthreads();
#pragma unroll
        for (int kk = 0; kk < 16; ++kk) {
            float4 a4 = *(const float4*)&As[kk][ty * 4];
            float4 b4 = *(const float4*)&Bs[kk][tx * 4];
            float2 b01 = make_float2(b4.x, b4.y), b23 = make_float2(b4.z, b4.w);
            acc[0][0] = ffma2(f2b(a4.x), b01, acc[0][0]); acc[0][1] = ffma2(f2b(a4.x), b23, acc[0][1]);
            acc[1][0] = ffma2(f2b(a4.y), b01, acc[1][0]); acc[1][1] = ffma2(f2b(a4.y), b23, acc[1][1]);
            acc[2][0] = ffma2(f2b(a4.z), b01, acc[2][0]); acc[2][1] = ffma2(f2b(a4.z), b23, acc[2][1]);
            acc[3][0] = ffma2(f2b(a4.w), b01, acc[3][0]); acc[3][1] = ffma2(f2b(a4.w), b23, acc[3][1]);
        }
    }
#pragma unroll
    for (int i = 0; i < 4; i++) {
        int m = m_blk + ty * 4 + i;
        float vals[4] = { acc[i][0].x, acc[i][0].y, acc[i][1].x, acc[i][1].y };
        float4 o;
#pragma unroll
        for (int jn = 0; jn < 4; jn++) {
            int n = n_blk + tx * 4 + jn;
            ((float*)&o)[jn] = vals[jn] + bias[n];
        }
        *(float4*)(C + (size_t)m * ldc + n_blk + tx * 4) = o;
    }
}

// ---------------- launch ---------------------------------------------------
extern "C" void kernel_launch(void* const* d_in, const int* in_sizes, int n_in,
                              void* d_out, int out_size) {
    const float* a    = (const float*)d_in[0];
    const float* z    = (const float*)d_in[1];
    const float* mask = (const float*)d_in[2];
    const float* g_a  = (const float*)d_in[3];
    const float* b_a  = (const float*)d_in[4];
    const float* g_z  = (const float*)d_in[5];
    const float* b_z  = (const float*)d_in[6];
    const float* w_z  = (const float*)d_in[7];
    const float* w_q  = (const float*)d_in[8];
    const float* w_k  = (const float*)d_in[9];
    const float* w_v  = (const float*)d_in[10];
    const float* w_g  = (const float*)d_in[11];
    const float* b_g  = (const float*)d_in[12];
    const float* w_o  = (const float*)d_in[13];
    const float* b_o  = (const float*)d_in[14];
    float* out = (float*)d_out;

    ln_a_kernel<<<N_TOK, 256>>>(a, g_a, b_a);

    dim3 g64(HDM / 64, N_TOK / 64);
    const float qscale = 0.14433756729740643f;  // 1/sqrt(48)
    proj_kernel<<<g64, 256>>>(w_q, 0,    1, (const float*)0, qscale);
    proj_kernel<<<g64, 256>>>(w_k, 768,  0, (const float*)0, 1.f);
    proj_kernel<<<g64, 256>>>(w_v, 1536, 0, (const float*)0, 1.f);
    proj_kernel<<<g64, 256>>>(w_g, 2304, 2, b_g, 1.f);

    pair_bias_kernel<<<dim3(N_TOK / 32, N_TOK), 256>>>(z, g_z, b_z, w_z, mask);

    scores_kernel<<<dim3(16, 32, 16), 256>>>();
    softmax_kernel<<<NH * N_TOK, 256>>>();
    pv_kernel<<<dim3(32, 16), 256>>>();

    out_proj_kernel<<<dim3(CQ / 64, N_TOK / 64), 256>>>(w_o, b_o, out);
}

// round 5
// speedup vs baseline: 1.1838x; 1.1838x over previous
#include <cuda_runtime.h>
#include <math.h>

#define N_TOK 1024
#define CQ    768
#define CZ    128
#define NH    16
#define HD    48
#define HDM   (NH*HD)              // 768
#define NN    ((size_t)N_TOK*(size_t)N_TOK)

// ---------------- scratch (device globals: no allocation allowed) ----------
__device__ float d_an[N_TOK*CQ];                    // LayerNorm(a)
__device__ float d_qkvg[(size_t)N_TOK*4*HDM];       // [tok][q|k|v|g] cols 0..3071
__device__ float d_pb[16ULL*1024ULL*1024ULL];       // pair bias (+mask bias)
__device__ float d_og[N_TOK*HDM];                   // gated attention output

// ---------------- f32x2 packed FMA (Blackwell FFMA2, PTX-only) -------------
__device__ __forceinline__ float2 ffma2(float2 a, float2 b, float2 c) {
    float2 d;
    asm("fma.rn.f32x2 %0, %1, %2, %3;"
        : "=l"(reinterpret_cast<unsigned long long&>(d))
        : "l"(reinterpret_cast<unsigned long long&>(a)),
          "l"(reinterpret_cast<unsigned long long&>(b)),
          "l"(reinterpret_cast<unsigned long long&>(c)));
    return d;
}
__device__ __forceinline__ float2 f2b(float x) { return make_float2(x, x); }

// ---------------- 1) LayerNorm over a: [1024][768] -------------------------
__global__ void ln_a_kernel(const float* __restrict__ a, const float* __restrict__ g,
                            const float* __restrict__ b) {
    int row = blockIdx.x, tid = threadIdx.x;
    const float* x = a + (size_t)row * CQ;
    float v0 = x[tid], v1 = x[tid + 256], v2 = x[tid + 512];
    float s = v0 + v1 + v2;
    float s2 = v0 * v0 + v1 * v1 + v2 * v2;
#pragma unroll
    for (int o = 16; o; o >>= 1) {
        s  += __shfl_xor_sync(0xffffffffu, s, o);
        s2 += __shfl_xor_sync(0xffffffffu, s2, o);
    }
    __shared__ float rs[8], rs2[8], bc[2];
    int w = tid >> 5;
    if ((tid & 31) == 0) { rs[w] = s; rs2[w] = s2; }
    __syncthreads();
    if (tid == 0) {
        float S = 0.f, S2 = 0.f;
        for (int i = 0; i < 8; i++) { S += rs[i]; S2 += rs2[i]; }
        float mu = S * (1.f / 768.f);
        float var = S2 * (1.f / 768.f) - mu * mu;
        bc[0] = mu; bc[1] = rsqrtf(var + 1e-5f);
    }
    __syncthreads();
    float mu = bc[0], rstd = bc[1];
    float* o = d_an + (size_t)row * CQ;
    o[tid]       = (v0 - mu) * rstd * g[tid]       + b[tid];
    o[tid + 256] = (v1 - mu) * rstd * g[tid + 256] + b[tid + 256];
    o[tid + 512] = (v2 - mu) * rstd * g[tid + 512] + b[tid + 512];
}

// ---------------- 2) fused q/k/v/g projections (grid.z selects weight) -----
// A = d_an [1024][768]; C = d_qkvg[:, sel*768 : sel*768+768]
__global__ void qkvg_proj_kernel(const float* __restrict__ wq, const float* __restrict__ wk,
                                 const float* __restrict__ wv, const float* __restrict__ wg,
                                 const float* __restrict__ bg) {
    __shared__ float As[16][68];
    __shared__ float Bs[16][64];
    const int K = CQ, N = HDM, ldc = 4 * HDM;
    int sel = blockIdx.z;
    const float* W = (sel == 0) ? wq : (sel == 1) ? wk : (sel == 2) ? wv : wg;
    int tid = threadIdx.x;
    int m_blk = blockIdx.y * 64, n_blk = blockIdx.x * 64;
    int tx = tid & 15, ty = tid >> 4;
    int ar = tid >> 2, ac4 = tid & 3;
    int br = tid >> 4, bc4 = tid & 15;
    const float* Ap = d_an + (size_t)(m_blk + ar) * K + ac4 * 4;
    const float* Wp = W + (size_t)br * N + n_blk + bc4 * 4;
    float2 acc[4][2];
#pragma unroll
    for (int i = 0; i < 4; i++) { acc[i][0] = make_float2(0.f, 0.f); acc[i][1] = make_float2(0.f, 0.f); }
    for (int k0 = 0; k0 < K; k0 += 16) {
        float4 av = *(const float4*)(Ap + k0);
        float4 bv = *(const float4*)(Wp + (size_t)k0 * N);
        __syncthreads();
        As[ac4 * 4 + 0][ar] = av.x; As[ac4 * 4 + 1][ar] = av.y;
        As[ac4 * 4 + 2][ar] = av.z; As[ac4 * 4 + 3][ar] = av.w;
        *(float4*)&Bs[br][bc4 * 4] = bv;
        __syncthreads();
#pragma unroll
        for (int kk = 0; kk < 16; ++kk) {
            float4 a4 = *(const float4*)&As[kk][ty * 4];
            float4 b4 = *(const float4*)&Bs[kk][tx * 4];
            float2 b01 = make_float2(b4.x, b4.y), b23 = make_float2(b4.z, b4.w);
            acc[0][0] = ffma2(f2b(a4.x), b01, acc[0][0]); acc[0][1] = ffma2(f2b(a4.x), b23, acc[0][1]);
            acc[1][0] = ffma2(f2b(a4.y), b01, acc[1][0]); acc[1][1] = ffma2(f2b(a4.y), b23, acc[1][1]);
            acc[2][0] = ffma2(f2b(a4.z), b01, acc[2][0]); acc[2][1] = ffma2(f2b(a4.z), b23, acc[2][1]);
            acc[3][0] = ffma2(f2b(a4.w), b01, acc[3][0]); acc[3][1] = ffma2(f2b(a4.w), b23, acc[3][1]);
        }
    }
    const float qscale = 0.14433756729740643f;  // 1/sqrt(48)
#pragma unroll
    for (int i = 0; i < 4; i++) {
        int m = m_blk + ty * 4 + i;
        float vals[4] = { acc[i][0].x, acc[i][0].y, acc[i][1].x, acc[i][1].y };
        float4 o;
#pragma unroll
        for (int jn = 0; jn < 4; jn++) {
            int n = n_blk + tx * 4 + jn;
            float v = vals[jn];
            if (sel == 0) v *= qscale;
            else if (sel == 3) v = 1.f / (1.f + __expf(-(v + bg[n])));
            ((float*)&o)[jn] = v;
        }
        *(float4*)(d_qkvg + (size_t)m * ldc + sel * 768 + n_blk + tx * 4) = o;
    }
}

// ---------------- 3) pair bias: fused LN(z) + zn@w_z + mask bias -----------
// block: fixed i, 128 j rows (4 tiles of 32). pb[h][i][j]
__global__ void pair_bias_kernel(const float* __restrict__ z, const float* __restrict__ gz,
                                 const float* __restrict__ bz, const float* __restrict__ wz,
                                 const float* __restrict__ mask) {
    __shared__ float zs[32][132];   // normalized z rows, padded
    __shared__ float2 wt[8][128];   // w_z transposed, head-pair packed
    int i = blockIdx.y;
    int tid = threadIdx.x;
    for (int idx = tid; idx < 1024; idx += 256) {
        int c = idx & 127, hp = idx >> 7;
        wt[hp][c] = make_float2(wz[c * 16 + 2 * hp], wz[c * 16 + 2 * hp + 1]);
    }
    int warp = tid >> 5, lane = tid & 31;
    float4 gq = *(const float4*)(gz + lane * 4);
    float4 bq = *(const float4*)(bz + lane * 4);
    float mi = mask[i];
    int jj = warp * 4 + (lane & 3);
    int hp2 = lane >> 2;

    for (int t = 0; t < 4; ++t) {
        int j0 = blockIdx.x * 128 + t * 32;
        __syncthreads();   // wt ready (t=0) / previous gemm done
#pragma unroll
        for (int rr = 0; rr < 4; ++rr) {
            int r = warp * 4 + rr;
            const float4 v = *(const float4*)(z + ((size_t)i * N_TOK + (j0 + r)) * CZ + lane * 4);
            float s  = v.x + v.y + v.z + v.w;
            float s2 = v.x * v.x + v.y * v.y + v.z * v.z + v.w * v.w;
#pragma unroll
            for (int o = 16; o; o >>= 1) {
                s  += __shfl_xor_sync(0xffffffffu, s, o);
                s2 += __shfl_xor_sync(0xffffffffu, s2, o);
            }
            float mu = s * (1.f / 128.f);
            float var = s2 * (1.f / 128.f) - mu * mu;
            float rstd = rsqrtf(var + 1e-5f);
            float4 o4;
            o4.x = (v.x - mu) * rstd * gq.x + bq.x;
            o4.y = (v.y - mu) * rstd * gq.y + bq.y;
            o4.z = (v.z - mu) * rstd * gq.z + bq.z;
            o4.w = (v.w - mu) * rstd * gq.w + bq.w;
            *(float4*)&zs[r][lane * 4] = o4;
        }
        __syncthreads();
        float2 acc = make_float2(0.f, 0.f);
#pragma unroll
        for (int c = 0; c < 128; c += 4) {
            float4 zq = *(const float4*)&zs[jj][c];
            acc = ffma2(f2b(zq.x), wt[hp2][c],     acc);
            acc = ffma2(f2b(zq.y), wt[hp2][c + 1], acc);
            acc = ffma2(f2b(zq.z), wt[hp2][c + 2], acc);
            acc = ffma2(f2b(zq.w), wt[hp2][c + 3], acc);
        }
        int j = j0 + jj;
        float mb = 1.0e9f * (mi * mask[j] - 1.0f);
        size_t base = (size_t)i * N_TOK + j;
        d_pb[(size_t)(2 * hp2) * NN + base]     = acc.x + mb;
        d_pb[(size_t)(2 * hp2 + 1) * NN + base] = acc.y + mb;
    }
}

// ---------------- 4) flash attention: scores + softmax + PV + gate ---------
// grid (16 q-tiles of 64, 16 heads), 256 threads.
// thread = (qp = tid>>3, dg = tid&7); rows rA=qp, rB=qp+32.
__global__ void __launch_bounds__(256) flash_kernel() {
    __shared__ float qs[48][68];
    __shared__ float ks[48][64];
    __shared__ float vs[64][48];
    __shared__ float ps[64][68];
    int q0 = blockIdx.x * 64, h = blockIdx.y;
    int tid = threadIdx.x;
    int qp = tid >> 3, dg = tid & 7;
    int rA = qp, rB = qp + 32;
    int d0 = dg * 6;

    // stage q transposed (q already pre-scaled by 1/sqrt(D))
    for (int idx = tid; idx < 64 * 12; idx += 256) {
        int r = idx / 12, c4 = idx % 12;
        float4 v = *(const float4*)(d_qkvg + (size_t)(q0 + r) * 3072 + h * 48 + c4 * 4);
        qs[c4 * 4 + 0][r] = v.x; qs[c4 * 4 + 1][r] = v.y;
        qs[c4 * 4 + 2][r] = v.z; qs[c4 * 4 + 3][r] = v.w;
    }

    float2 oA0 = make_float2(0.f, 0.f), oA1 = oA0, oA2 = oA0;
    float2 oB0 = oA0, oB1 = oA0, oB2 = oA0;
    float mA = -1e30f, lA = 0.f, mB = -1e30f, lB = 0.f;

    for (int k0 = 0; k0 < N_TOK; k0 += 64) {
        __syncthreads();   // previous PV done: safe to overwrite ks/vs
        for (int idx = tid; idx < 64 * 12; idx += 256) {
            int r = idx / 12, c4 = idx % 12;
            float4 kv = *(const float4*)(d_qkvg + (size_t)(k0 + r) * 3072 + 768 + h * 48 + c4 * 4);
            ks[c4 * 4 + 0][r] = kv.x; ks[c4 * 4 + 1][r] = kv.y;
            ks[c4 * 4 + 2][r] = kv.z; ks[c4 * 4 + 3][r] = kv.w;
            *(float4*)&vs[r][c4 * 4] =
                *(const float4*)(d_qkvg + (size_t)(k0 + r) * 3072 + 1536 + h * 48 + c4 * 4);
        }
        // pb tile rows (streamed from global, coalesced)
        size_t pbase = (size_t)h * NN + (size_t)q0 * N_TOK + k0 + dg * 8;
        float4 pA0 = *(const float4*)(d_pb + pbase + (size_t)rA * N_TOK);
        float4 pA1 = *(const float4*)(d_pb + pbase + (size_t)rA * N_TOK + 4);
        float4 pB0 = *(const float4*)(d_pb + pbase + (size_t)rB * N_TOK);
        float4 pB1 = *(const float4*)(d_pb + pbase + (size_t)rB * N_TOK + 4);
        __syncthreads();   // tiles staged

        float2 sA[4] = { make_float2(pA0.x, pA0.y), make_float2(pA0.z, pA0.w),
                         make_float2(pA1.x, pA1.y), make_float2(pA1.z, pA1.w) };
        float2 sB[4] = { make_float2(pB0.x, pB0.y), make_float2(pB0.z, pB0.w),
                         make_float2(pB1.x, pB1.y), make_float2(pB1.z, pB1.w) };
#pragma unroll 12
        for (int d = 0; d < 48; ++d) {
            float4 ka = *(const float4*)&ks[d][dg * 8];
            float4 kb = *(const float4*)&ks[d][dg * 8 + 4];
            float2 k01 = make_float2(ka.x, ka.y), k23 = make_float2(ka.z, ka.w);
            float2 k45 = make_float2(kb.x, kb.y), k67 = make_float2(kb.z, kb.w);
            float2 qa = f2b(qs[d][rA]);
            float2 qb = f2b(qs[d][rB]);
            sA[0] = ffma2(qa, k01, sA[0]); sA[1] = ffma2(qa, k23, sA[1]);
            sA[2] = ffma2(qa, k45, sA[2]); sA[3] = ffma2(qa, k67, sA[3]);
            sB[0] = ffma2(qb, k01, sB[0]); sB[1] = ffma2(qb, k23, sB[1]);
            sB[2] = ffma2(qb, k45, sB[2]); sB[3] = ffma2(qb, k67, sB[3]);
        }
        // tile max per row
        float tmA = fmaxf(fmaxf(fmaxf(sA[0].x, sA[0].y), fmaxf(sA[1].x, sA[1].y)),
                          fmaxf(fmaxf(sA[2].x, sA[2].y), fmaxf(sA[3].x, sA[3].y)));
        float tmB = fmaxf(fmaxf(fmaxf(sB[0].x, sB[0].y), fmaxf(sB[1].x, sB[1].y)),
                          fmaxf(fmaxf(sB[2].x, sB[2].y), fmaxf(sB[3].x, sB[3].y)));
#pragma unroll
        for (int o = 1; o < 8; o <<= 1) {
            tmA = fmaxf(tmA, __shfl_xor_sync(0xffffffffu, tmA, o));
            tmB = fmaxf(tmB, __shfl_xor_sync(0xffffffffu, tmB, o));
        }
        float mAn = fmaxf(mA, tmA), mBn = fmaxf(mB, tmB);
        float scA = __expf(mA - mAn), scB = __expf(mB - mBn);
        float sumA = 0.f, sumB = 0.f;
#pragma unroll
        for (int jj = 0; jj < 4; ++jj) {
            float2 eA, eB;
            eA.x = __expf(sA[jj].x - mAn); eA.y = __expf(sA[jj].y - mAn);
            eB.x = __expf(sB[jj].x - mBn); eB.y = __expf(sB[jj].y - mBn);
            sumA += eA.x + eA.y; sumB += eB.x + eB.y;
            *(float2*)&ps[rA][dg * 8 + jj * 2] = eA;
            *(float2*)&ps[rB][dg * 8 + jj * 2] = eB;
        }
#pragma unroll
        for (int o = 1; o < 8; o <<= 1) {
            sumA += __shfl_xor_sync(0xffffffffu, sumA, o);
            sumB += __shfl_xor_sync(0xffffffffu, sumB, o);
        }
        lA = lA * scA + sumA; mA = mAn;
        lB = lB * scB + sumB; mB = mBn;
        oA0.x *= scA; oA0.y *= scA; oA1.x *= scA; oA1.y *= scA; oA2.x *= scA; oA2.y *= scA;
        oB0.x *= scB; oB0.y *= scB; oB1.x *= scB; oB1.y *= scB; oB2.x *= scB; oB2.y *= scB;
        __syncthreads();   // ps ready
#pragma unroll 16
        for (int kk = 0; kk < 64; ++kk) {
            float2 v01 = *(const float2*)&vs[kk][d0];
            float2 v23 = *(const float2*)&vs[kk][d0 + 2];
            float2 v45 = *(const float2*)&vs[kk][d0 + 4];
            float2 pa = f2b(ps[rA][kk]);
            float2 pbv = f2b(ps[rB][kk]);
            oA0 = ffma2(pa, v01, oA0); oA1 = ffma2(pa, v23, oA1); oA2 = ffma2(pa, v45, oA2);
            oB0 = ffma2(pbv, v01, oB0); oB1 = ffma2(pbv, v23, oB1); oB2 = ffma2(pbv, v45, oB2);
        }
    }
    // finalize: normalize, gate, store
    float invA = 1.f / lA, invB = 1.f / lB;
    const float* gpA = d_qkvg + (size_t)(q0 + rA) * 3072 + 2304 + h * 48 + d0;
    const float* gpB = d_qkvg + (size_t)(q0 + rB) * 3072 + 2304 + h * 48 + d0;
    float* opA = d_og + (size_t)(q0 + rA) * HDM + h * 48 + d0;
    float* opB = d_og + (size_t)(q0 + rB) * HDM + h * 48 + d0;
    opA[0] = oA0.x * invA * gpA[0]; opA[1] = oA0.y * invA * gpA[1];
    opA[2] = oA1.x * invA * gpA[2]; opA[3] = oA1.y * invA * gpA[3];
    opA[4] = oA2.x * invA * gpA[4]; opA[5] = oA2.y * invA * gpA[5];
    opB[0] = oB0.x * invB * gpB[0]; opB[1] = oB0.y * invB * gpB[1];
    opB[2] = oB1.x * invB * gpB[2]; opB[3] = oB1.y * invB * gpB[3];
    opB[4] = oB2.x * invB * gpB[4]; opB[5] = oB2.y * invB * gpB[5];
}

// ---------------- 5) output projection: og @ w_o + b_o ---------------------
__global__ void out_proj_kernel(const float* __restrict__ W, const float* __restrict__ bias,
                                float* __restrict__ C) {
    __shared__ float As[16][68];
    __shared__ float Bs[16][64];
    const int K = HDM, N = CQ, ldc = CQ;
    int tid = threadIdx.x;
    int m_blk = blockIdx.y * 64, n_blk = blockIdx.x * 64;
    int tx = tid & 15, ty = tid >> 4;
    int ar = tid >> 2, ac4 = tid & 3;
    int br = tid >> 4, bc4 = tid & 15;
    const float* Ap = d_og + (size_t)(m_blk + ar) * K + ac4 * 4;
    const float* Wp = W + (size_t)br * N + n_blk + bc4 * 4;
    float2 acc[4][2];
#pragma unroll
    for (int i = 0; i < 4; i++) { acc[i][0] = make_float2(0.f, 0.f); acc[i][1] = make_float2(0.f, 0.f); }
    for (int k0 = 0; k0 < K; k0 += 16) {
        float4 av = *(const float4*)(Ap + k0);
        float4 bv = *(const float4*)(Wp + (size_t)k0 * N);
        __syncthreads();
        As[ac4 * 4 + 0][ar] = av.x; As[ac4 * 4 + 1][ar] = av.y;
        As[ac4 * 4 + 2][ar] = av.z; As[ac4 * 4 + 3][ar] = av.w;
        *(float4*)&Bs[br][bc4 * 4] = bv;
        __syncthreads();
#pragma unroll
        for (int kk = 0; kk < 16; ++kk) {
            float4 a4 = *(const float4*)&As[kk][ty * 4];
            float4 b4 = *(const float4*)&Bs[kk][tx * 4];
            float2 b01 = make_float2(b4.x, b4.y), b23 = make_float2(b4.z, b4.w);
            acc[0][0] = ffma2(f2b(a4.x), b01, acc[0][0]); acc[0][1] = ffma2(f2b(a4.x), b23, acc[0][1]);
            acc[1][0] = ffma2(f2b(a4.y), b01, acc[1][0]); acc[1][1] = ffma2(f2b(a4.y), b23, acc[1][1]);
            acc[2][0] = ffma2(f2b(a4.z), b01, acc[2][0]); acc[2][1] = ffma2(f2b(a4.z), b23, acc[2][1]);
            acc[3][0] = ffma2(f2b(a4.w), b01, acc[3][0]); acc[3][1] = ffma2(f2b(a4.w), b23, acc[3][1]);
        }
    }
#pragma unroll
    for (int i = 0; i < 4; i++) {
        int m = m_blk + ty * 4 + i;
        float vals[4] = { acc[i][0].x, acc[i][0].y, acc[i][1].x, acc[i][1].y };
        float4 o;
#pragma unroll
        for (int jn = 0; jn < 4; jn++) {
            int n = n_blk + tx * 4 + jn;
            ((float*)&o)[jn] = vals[jn] + bias[n];
        }
        *(float4*)(C + (size_t)m * ldc + n_blk + tx * 4) = o;
    }
}

// ---------------- launch ---------------------------------------------------
extern "C" void kernel_launch(void* const* d_in, const int* in_sizes, int n_in,
                              void* d_out, int out_size) {
    const float* a    = (const float*)d_in[0];
    const float* z    = (const float*)d_in[1];
    const float* mask = (const float*)d_in[2];
    const float* g_a  = (const float*)d_in[3];
    const float* b_a  = (const float*)d_in[4];
    const float* g_z  = (const float*)d_in[5];
    const float* b_z  = (const float*)d_in[6];
    const float* w_z  = (const float*)d_in[7];
    const float* w_q  = (const float*)d_in[8];
    const float* w_k  = (const float*)d_in[9];
    const float* w_v  = (const float*)d_in[10];
    const float* w_g  = (const float*)d_in[11];
    const float* b_g  = (const float*)d_in[12];
    const float* w_o  = (const float*)d_in[13];
    const float* b_o  = (const float*)d_in[14];
    float* out = (float*)d_out;

    ln_a_kernel<<<N_TOK, 256>>>(a, g_a, b_a);

    qkvg_proj_kernel<<<dim3(HDM / 64, N_TOK / 64, 4), 256>>>(w_q, w_k, w_v, w_g, b_g);

    pair_bias_kernel<<<dim3(N_TOK / 128, N_TOK), 256>>>(z, g_z, b_z, w_z, mask);

    flash_kernel<<<dim3(N_TOK / 64, NH), 256>>>();

    out_proj_kernel<<<dim3(CQ / 64, N_TOK / 64), 256>>>(w_o, b_o, out);
}

// round 6
// speedup vs baseline: 1.8229x; 1.5399x over previous
#include <cuda_runtime.h>
#include <math.h>

#define N_TOK 1024
#define CQ    768
#define CZ    128
#define NH    16
#define HD    48
#define HDM   (NH*HD)              // 768
#define NN    ((size_t)N_TOK*(size_t)N_TOK)
#define KSPLIT 4

// ---------------- scratch (device globals: no allocation allowed) ----------
__device__ float d_an[N_TOK*CQ];                    // LayerNorm(a)
__device__ float d_qkvg[(size_t)N_TOK*4*HDM];       // [tok][q|k|v|g]
__device__ float d_pb[16ULL*1024ULL*1024ULL];       // pair bias (+mask bias)
__device__ float d_og[N_TOK*HDM];                   // gated attention output
__device__ float d_ospl[(size_t)KSPLIT*NH*N_TOK*HD];// split-k partial o (unnormalized)
__device__ float d_ml[(size_t)KSPLIT*NH*N_TOK*2];   // split-k partial (m, l)

// ---------------- f32x2 packed FMA (Blackwell FFMA2, PTX-only) -------------
__device__ __forceinline__ float2 ffma2(float2 a, float2 b, float2 c) {
    float2 d;
    asm("fma.rn.f32x2 %0, %1, %2, %3;"
        : "=l"(reinterpret_cast<unsigned long long&>(d))
        : "l"(reinterpret_cast<unsigned long long&>(a)),
          "l"(reinterpret_cast<unsigned long long&>(b)),
          "l"(reinterpret_cast<unsigned long long&>(c)));
    return d;
}
__device__ __forceinline__ float2 f2b(float x) { return make_float2(x, x); }

// ---------------- 1) LayerNorm over a: [1024][768] -------------------------
__global__ void ln_a_kernel(const float* __restrict__ a, const float* __restrict__ g,
                            const float* __restrict__ b) {
    int row = blockIdx.x, tid = threadIdx.x;
    const float* x = a + (size_t)row * CQ;
    float v0 = x[tid], v1 = x[tid + 256], v2 = x[tid + 512];
    float s = v0 + v1 + v2;
    float s2 = v0 * v0 + v1 * v1 + v2 * v2;
#pragma unroll
    for (int o = 16; o; o >>= 1) {
        s  += __shfl_xor_sync(0xffffffffu, s, o);
        s2 += __shfl_xor_sync(0xffffffffu, s2, o);
    }
    __shared__ float rs[8], rs2[8], bc[2];
    int w = tid >> 5;
    if ((tid & 31) == 0) { rs[w] = s; rs2[w] = s2; }
    __syncthreads();
    if (tid == 0) {
        float S = 0.f, S2 = 0.f;
        for (int i = 0; i < 8; i++) { S += rs[i]; S2 += rs2[i]; }
        float mu = S * (1.f / 768.f);
        float var = S2 * (1.f / 768.f) - mu * mu;
        bc[0] = mu; bc[1] = rsqrtf(var + 1e-5f);
    }
    __syncthreads();
    float mu = bc[0], rstd = bc[1];
    float* o = d_an + (size_t)row * CQ;
    o[tid]       = (v0 - mu) * rstd * g[tid]       + b[tid];
    o[tid + 256] = (v1 - mu) * rstd * g[tid + 256] + b[tid + 256];
    o[tid + 512] = (v2 - mu) * rstd * g[tid + 512] + b[tid + 512];
}

// ---------------- 2) fused q/k/v/g projections (grid.z selects weight) -----
__global__ void qkvg_proj_kernel(const float* __restrict__ wq, const float* __restrict__ wk,
                                 const float* __restrict__ wv, const float* __restrict__ wg,
                                 const float* __restrict__ bg) {
    __shared__ float As[16][68];
    __shared__ float Bs[16][64];
    const int K = CQ, N = HDM, ldc = 4 * HDM;
    int sel = blockIdx.z;
    const float* W = (sel == 0) ? wq : (sel == 1) ? wk : (sel == 2) ? wv : wg;
    int tid = threadIdx.x;
    int m_blk = blockIdx.y * 64, n_blk = blockIdx.x * 64;
    int tx = tid & 15, ty = tid >> 4;
    int ar = tid >> 2, ac4 = tid & 3;
    int br = tid >> 4, bc4 = tid & 15;
    const float* Ap = d_an + (size_t)(m_blk + ar) * K + ac4 * 4;
    const float* Wp = W + (size_t)br * N + n_blk + bc4 * 4;
    float2 acc[4][2];
#pragma unroll
    for (int i = 0; i < 4; i++) { acc[i][0] = make_float2(0.f, 0.f); acc[i][1] = make_float2(0.f, 0.f); }
    for (int k0 = 0; k0 < K; k0 += 16) {
        float4 av = *(const float4*)(Ap + k0);
        float4 bv = *(const float4*)(Wp + (size_t)k0 * N);
        __syncthreads();
        As[ac4 * 4 + 0][ar] = av.x; As[ac4 * 4 + 1][ar] = av.y;
        As[ac4 * 4 + 2][ar] = av.z; As[ac4 * 4 + 3][ar] = av.w;
        *(float4*)&Bs[br][bc4 * 4] = bv;
        __syncthreads();
#pragma unroll
        for (int kk = 0; kk < 16; ++kk) {
            float4 a4 = *(const float4*)&As[kk][ty * 4];
            float4 b4 = *(const float4*)&Bs[kk][tx * 4];
            float2 b01 = make_float2(b4.x, b4.y), b23 = make_float2(b4.z, b4.w);
            acc[0][0] = ffma2(f2b(a4.x), b01, acc[0][0]); acc[0][1] = ffma2(f2b(a4.x), b23, acc[0][1]);
            acc[1][0] = ffma2(f2b(a4.y), b01, acc[1][0]); acc[1][1] = ffma2(f2b(a4.y), b23, acc[1][1]);
            acc[2][0] = ffma2(f2b(a4.z), b01, acc[2][0]); acc[2][1] = ffma2(f2b(a4.z), b23, acc[2][1]);
            acc[3][0] = ffma2(f2b(a4.w), b01, acc[3][0]); acc[3][1] = ffma2(f2b(a4.w), b23, acc[3][1]);
        }
    }
    const float qscale = 0.14433756729740643f;  // 1/sqrt(48)
#pragma unroll
    for (int i = 0; i < 4; i++) {
        int m = m_blk + ty * 4 + i;
        float vals[4] = { acc[i][0].x, acc[i][0].y, acc[i][1].x, acc[i][1].y };
        float4 o;
#pragma unroll
        for (int jn = 0; jn < 4; jn++) {
            int n = n_blk + tx * 4 + jn;
            float v = vals[jn];
            if (sel == 0) v *= qscale;
            else if (sel == 3) v = 1.f / (1.f + __expf(-(v + bg[n])));
            ((float*)&o)[jn] = v;
        }
        *(float4*)(d_qkvg + (size_t)m * ldc + sel * 768 + n_blk + tx * 4) = o;
    }
}

// ---------------- 3) pair bias: fused LN(z) + zn@w_z + mask bias -----------
// block: fixed i, 64 j rows. pb[h][i][j]. Conflict-free wt (stride 130 pairs).
__global__ void __launch_bounds__(256) pair_bias_kernel(
        const float* __restrict__ z, const float* __restrict__ gz,
        const float* __restrict__ bz, const float* __restrict__ wz,
        const float* __restrict__ mask) {
    __shared__ float zs[64][132];      // normalized z rows (also reused as stage)
    __shared__ float2 wt[8][130];      // w_z head-pair packed, padded stride
    int i = blockIdx.y;
    int j0 = blockIdx.x * 64;
    int tid = threadIdx.x;
    int warp = tid >> 5, lane = tid & 31;

    for (int idx = tid; idx < 1024; idx += 256) {
        int c = idx & 127, hp = idx >> 7;
        wt[hp][c] = make_float2(wz[c * 16 + 2 * hp], wz[c * 16 + 2 * hp + 1]);
    }
    float4 gq = *(const float4*)(gz + lane * 4);
    float4 bq = *(const float4*)(bz + lane * 4);

    // LN: 8 rows per warp
#pragma unroll
    for (int rr = 0; rr < 8; ++rr) {
        int r = warp * 8 + rr;
        const float4 v = *(const float4*)(z + ((size_t)i * N_TOK + (j0 + r)) * CZ + lane * 4);
        float s  = v.x + v.y + v.z + v.w;
        float s2 = v.x * v.x + v.y * v.y + v.z * v.z + v.w * v.w;
#pragma unroll
        for (int o = 16; o; o >>= 1) {
            s  += __shfl_xor_sync(0xffffffffu, s, o);
            s2 += __shfl_xor_sync(0xffffffffu, s2, o);
        }
        float mu = s * (1.f / 128.f);
        float var = s2 * (1.f / 128.f) - mu * mu;
        float rstd = rsqrtf(var + 1e-5f);
        float4 o4;
        o4.x = (v.x - mu) * rstd * gq.x + bq.x;
        o4.y = (v.y - mu) * rstd * gq.y + bq.y;
        o4.z = (v.z - mu) * rstd * gq.z + bq.z;
        o4.w = (v.w - mu) * rstd * gq.w + bq.w;
        *(float4*)&zs[r][lane * 4] = o4;
    }
    __syncthreads();

    // GEMM: thread owns rows (jg*2, jg*2+1) x head-pair hp
    int jg = tid >> 3, hp = tid & 7;
    int ja = jg * 2, jb = ja + 1;
    float2 accA = make_float2(0.f, 0.f), accB = accA;
#pragma unroll
    for (int c = 0; c < 128; c += 4) {
        float4 w01 = *(const float4*)&wt[hp][c];      // pairs for c, c+1
        float4 w23 = *(const float4*)&wt[hp][c + 2];  // pairs for c+2, c+3
        float4 za = *(const float4*)&zs[ja][c];
        float4 zb = *(const float4*)&zs[jb][c];
        float2 wA = make_float2(w01.x, w01.y), wB = make_float2(w01.z, w01.w);
        float2 wC = make_float2(w23.x, w23.y), wD = make_float2(w23.z, w23.w);
        accA = ffma2(f2b(za.x), wA, accA); accA = ffma2(f2b(za.y), wB, accA);
        accA = ffma2(f2b(za.z), wC, accA); accA = ffma2(f2b(za.w), wD, accA);
        accB = ffma2(f2b(zb.x), wA, accB); accB = ffma2(f2b(zb.y), wB, accB);
        accB = ffma2(f2b(zb.z), wC, accB); accB = ffma2(f2b(zb.w), wD, accB);
    }
    __syncthreads();          // done reading zs; reuse as stage [16][66]
    float* stage = &zs[0][0];
    stage[(2 * hp) * 66 + ja]     = accA.x;
    stage[(2 * hp + 1) * 66 + ja] = accA.y;
    stage[(2 * hp) * 66 + jb]     = accB.x;
    stage[(2 * hp + 1) * 66 + jb] = accB.y;
    __syncthreads();
    // coalesced output: thread -> (h = tid>>4, j4 = (tid&15)*4)
    int h = tid >> 4, j4 = (tid & 15) * 4;
    float mi = mask[i];
    float4 mj = *(const float4*)(mask + j0 + j4);
    float4 o;
    o.x = stage[h * 66 + j4 + 0] + 1.0e9f * (mi * mj.x - 1.0f);
    o.y = stage[h * 66 + j4 + 1] + 1.0e9f * (mi * mj.y - 1.0f);
    o.z = stage[h * 66 + j4 + 2] + 1.0e9f * (mi * mj.z - 1.0f);
    o.w = stage[h * 66 + j4 + 3] + 1.0e9f * (mi * mj.w - 1.0f);
    *(float4*)(d_pb + (size_t)h * NN + (size_t)i * N_TOK + j0 + j4) = o;
}

// ---------------- 4) split-k flash attention ------------------------------
// grid (16 q-tiles, 16 heads, KSPLIT). Partial (o, m, l) per split.
__global__ void __launch_bounds__(256) flash_kernel() {
    __shared__ float qs[48][68];
    __shared__ float ks[48][64];
    __shared__ float vs[64][48];
    __shared__ float ps[64][68];
    int q0 = blockIdx.x * 64, h = blockIdx.y, split = blockIdx.z;
    int tid = threadIdx.x;
    int qp = tid >> 3, dg = tid & 7;
    int rA = qp, rB = qp + 32;
    int d0 = dg * 6;

    for (int idx = tid; idx < 64 * 12; idx += 256) {
        int r = idx / 12, c4 = idx % 12;
        float4 v = *(const float4*)(d_qkvg + (size_t)(q0 + r) * 3072 + h * 48 + c4 * 4);
        qs[c4 * 4 + 0][r] = v.x; qs[c4 * 4 + 1][r] = v.y;
        qs[c4 * 4 + 2][r] = v.z; qs[c4 * 4 + 3][r] = v.w;
    }

    float2 oA0 = make_float2(0.f, 0.f), oA1 = oA0, oA2 = oA0;
    float2 oB0 = oA0, oB1 = oA0, oB2 = oA0;
    float mA = -1e30f, lA = 0.f, mB = -1e30f, lB = 0.f;

    int kbeg = split * (N_TOK / KSPLIT), kend = kbeg + (N_TOK / KSPLIT);
    for (int k0 = kbeg; k0 < kend; k0 += 64) {
        __syncthreads();
        for (int idx = tid; idx < 64 * 12; idx += 256) {
            int r = idx / 12, c4 = idx % 12;
            float4 kv = *(const float4*)(d_qkvg + (size_t)(k0 + r) * 3072 + 768 + h * 48 + c4 * 4);
            ks[c4 * 4 + 0][r] = kv.x; ks[c4 * 4 + 1][r] = kv.y;
            ks[c4 * 4 + 2][r] = kv.z; ks[c4 * 4 + 3][r] = kv.w;
            *(float4*)&vs[r][c4 * 4] =
                *(const float4*)(d_qkvg + (size_t)(k0 + r) * 3072 + 1536 + h * 48 + c4 * 4);
        }
        size_t pbase = (size_t)h * NN + (size_t)q0 * N_TOK + k0 + dg * 8;
        float4 pA0 = *(const float4*)(d_pb + pbase + (size_t)rA * N_TOK);
        float4 pA1 = *(const float4*)(d_pb + pbase + (size_t)rA * N_TOK + 4);
        float4 pB0 = *(const float4*)(d_pb + pbase + (size_t)rB * N_TOK);
        float4 pB1 = *(const float4*)(d_pb + pbase + (size_t)rB * N_TOK + 4);
        __syncthreads();

        float2 sA[4] = { make_float2(pA0.x, pA0.y), make_float2(pA0.z, pA0.w),
                         make_float2(pA1.x, pA1.y), make_float2(pA1.z, pA1.w) };
        float2 sB[4] = { make_float2(pB0.x, pB0.y), make_float2(pB0.z, pB0.w),
                         make_float2(pB1.x, pB1.y), make_float2(pB1.z, pB1.w) };
#pragma unroll 12
        for (int d = 0; d < 48; ++d) {
            float4 ka = *(const float4*)&ks[d][dg * 8];
            float4 kb = *(const float4*)&ks[d][dg * 8 + 4];
            float2 k01 = make_float2(ka.x, ka.y), k23 = make_float2(ka.z, ka.w);
            float2 k45 = make_float2(kb.x, kb.y), k67 = make_float2(kb.z, kb.w);
            float2 qa = f2b(qs[d][rA]);
            float2 qb = f2b(qs[d][rB]);
            sA[0] = ffma2(qa, k01, sA[0]); sA[1] = ffma2(qa, k23, sA[1]);
            sA[2] = ffma2(qa, k45, sA[2]); sA[3] = ffma2(qa, k67, sA[3]);
            sB[0] = ffma2(qb, k01, sB[0]); sB[1] = ffma2(qb, k23, sB[1]);
            sB[2] = ffma2(qb, k45, sB[2]); sB[3] = ffma2(qb, k67, sB[3]);
        }
        float tmA = fmaxf(fmaxf(fmaxf(sA[0].x, sA[0].y), fmaxf(sA[1].x, sA[1].y)),
                          fmaxf(fmaxf(sA[2].x, sA[2].y), fmaxf(sA[3].x, sA[3].y)));
        float tmB = fmaxf(fmaxf(fmaxf(sB[0].x, sB[0].y), fmaxf(sB[1].x, sB[1].y)),
                          fmaxf(fmaxf(sB[2].x, sB[2].y), fmaxf(sB[3].x, sB[3].y)));
#pragma unroll
        for (int o = 1; o < 8; o <<= 1) {
            tmA = fmaxf(tmA, __shfl_xor_sync(0xffffffffu, tmA, o));
            tmB = fmaxf(tmB, __shfl_xor_sync(0xffffffffu, tmB, o));
        }
        float mAn = fmaxf(mA, tmA), mBn = fmaxf(mB, tmB);
        float scA = __expf(mA - mAn), scB = __expf(mB - mBn);
        float sumA = 0.f, sumB = 0.f;
#pragma unroll
        for (int jj = 0; jj < 4; ++jj) {
            float2 eA, eB;
            eA.x = __expf(sA[jj].x - mAn); eA.y = __expf(sA[jj].y - mAn);
            eB.x = __expf(sB[jj].x - mBn); eB.y = __expf(sB[jj].y - mBn);
            sumA += eA.x + eA.y; sumB += eB.x + eB.y;
            *(float2*)&ps[rA][dg * 8 + jj * 2] = eA;
            *(float2*)&ps[rB][dg * 8 + jj * 2] = eB;
        }
#pragma unroll
        for (int o = 1; o < 8; o <<= 1) {
            sumA += __shfl_xor_sync(0xffffffffu, sumA, o);
            sumB += __shfl_xor_sync(0xffffffffu, sumB, o);
        }
        lA = lA * scA + sumA; mA = mAn;
        lB = lB * scB + sumB; mB = mBn;
        oA0.x *= scA; oA0.y *= scA; oA1.x *= scA; oA1.y *= scA; oA2.x *= scA; oA2.y *= scA;
        oB0.x *= scB; oB0.y *= scB; oB1.x *= scB; oB1.y *= scB; oB2.x *= scB; oB2.y *= scB;
        __syncthreads();
#pragma unroll 16
        for (int kk = 0; kk < 64; ++kk) {
            float2 v01 = *(const float2*)&vs[kk][d0];
            float2 v23 = *(const float2*)&vs[kk][d0 + 2];
            float2 v45 = *(const float2*)&vs[kk][d0 + 4];
            float2 pa = f2b(ps[rA][kk]);
            float2 pbv = f2b(ps[rB][kk]);
            oA0 = ffma2(pa, v01, oA0); oA1 = ffma2(pa, v23, oA1); oA2 = ffma2(pa, v45, oA2);
            oB0 = ffma2(pbv, v01, oB0); oB1 = ffma2(pbv, v23, oB1); oB2 = ffma2(pbv, v45, oB2);
        }
    }
    // store unnormalized partials
    size_t obase = ((size_t)split * NH + h) * N_TOK;
    float* opA = d_ospl + (obase + q0 + rA) * HD + d0;
    float* opB = d_ospl + (obase + q0 + rB) * HD + d0;
    opA[0] = oA0.x; opA[1] = oA0.y; opA[2] = oA1.x;
    opA[3] = oA1.y; opA[4] = oA2.x; opA[5] = oA2.y;
    opB[0] = oB0.x; opB[1] = oB0.y; opB[2] = oB1.x;
    opB[3] = oB1.y; opB[4] = oB2.x; opB[5] = oB2.y;
    if (dg == 0) {
        d_ml[(obase + q0 + rA) * 2]     = mA;
        d_ml[(obase + q0 + rA) * 2 + 1] = lA;
        d_ml[(obase + q0 + rB) * 2]     = mB;
        d_ml[(obase + q0 + rB) * 2 + 1] = lB;
    }
}

// ---------------- 4b) combine splits + gate --------------------------------
__global__ void combine_kernel() {
    int idx = blockIdx.x * 256 + threadIdx.x;        // 16*1024*48
    int d = idx % HD;
    int hq = idx / HD;
    int q = hq & (N_TOK - 1);
    int h = hq >> 10;
    size_t row = (size_t)h * N_TOK + q;
    float m[KSPLIT], l[KSPLIT];
    float mx = -1e30f;
#pragma unroll
    for (int s = 0; s < KSPLIT; ++s) {
        m[s] = d_ml[((size_t)s * NH * N_TOK + row) * 2];
        l[s] = d_ml[((size_t)s * NH * N_TOK + row) * 2 + 1];
        mx = fmaxf(mx, m[s]);
    }
    float lt = 0.f, ov = 0.f;
#pragma unroll
    for (int s = 0; s < KSPLIT; ++s) {
        float w = __expf(m[s] - mx);
        lt += l[s] * w;
        ov += d_ospl[((size_t)s * NH * N_TOK + row) * HD + d] * w;
    }
    float g = d_qkvg[(size_t)q * 3072 + 2304 + h * 48 + d];
    d_og[(size_t)q * HDM + h * 48 + d] = ov / lt * g;
}

// ---------------- 5) output projection: og @ w_o + b_o (32x64 tiles) -------
__global__ void out_proj_kernel(const float* __restrict__ W, const float* __restrict__ bias,
                                float* __restrict__ C) {
    __shared__ float As[16][36];
    __shared__ float Bs[16][64];
    const int K = HDM, N = CQ, ldc = CQ;
    int tid = threadIdx.x;
    int m_blk = blockIdx.y * 32, n_blk = blockIdx.x * 64;
    int tx = tid & 15, ty = tid >> 4;
    int ar = tid >> 3, ac2 = tid & 7;
    int br = tid >> 4, bc4 = tid & 15;
    const float* Ap = d_og + (size_t)(m_blk + ar) * K + ac2 * 2;
    const float* Wp = W + (size_t)br * N + n_blk + bc4 * 4;
    float2 acc[2][2];
#pragma unroll
    for (int i = 0; i < 2; i++) { acc[i][0] = make_float2(0.f, 0.f); acc[i][1] = make_float2(0.f, 0.f); }
    for (int k0 = 0; k0 < K; k0 += 16) {
        float2 av = *(const float2*)(Ap + k0);
        float4 bv = *(const float4*)(Wp + (size_t)k0 * N);
        __syncthreads();
        As[ac2 * 2 + 0][ar] = av.x;
        As[ac2 * 2 + 1][ar] = av.y;
        *(float4*)&Bs[br][bc4 * 4] = bv;
        __syncthreads();
#pragma unroll
        for (int kk = 0; kk < 16; ++kk) {
            float2 a2 = *(const float2*)&As[kk][ty * 2];
            float4 b4 = *(const float4*)&Bs[kk][tx * 4];
            float2 b01 = make_float2(b4.x, b4.y), b23 = make_float2(b4.z, b4.w);
            acc[0][0] = ffma2(f2b(a2.x), b01, acc[0][0]); acc[0][1] = ffma2(f2b(a2.x), b23, acc[0][1]);
            acc[1][0] = ffma2(f2b(a2.y), b01, acc[1][0]); acc[1][1] = ffma2(f2b(a2.y), b23, acc[1][1]);
        }
    }
#pragma unroll
    for (int i = 0; i < 2; i++) {
        int m = m_blk + ty * 2 + i;
        float vals[4] = { acc[i][0].x, acc[i][0].y, acc[i][1].x, acc[i][1].y };
        float4 o;
#pragma unroll
        for (int jn = 0; jn < 4; jn++) {
            int n = n_blk + tx * 4 + jn;
            ((float*)&o)[jn] = vals[jn] + bias[n];
        }
        *(float4*)(C + (size_t)m * ldc + n_blk + tx * 4) = o;
    }
}

// ---------------- launch ---------------------------------------------------
extern "C" void kernel_launch(void* const* d_in, const int* in_sizes, int n_in,
                              void* d_out, int out_size) {
    const float* a    = (const float*)d_in[0];
    const float* z    = (const float*)d_in[1];
    const float* mask = (const float*)d_in[2];
    const float* g_a  = (const float*)d_in[3];
    const float* b_a  = (const float*)d_in[4];
    const float* g_z  = (const float*)d_in[5];
    const float* b_z  = (const float*)d_in[6];
    const float* w_z  = (const float*)d_in[7];
    const float* w_q  = (const float*)d_in[8];
    const float* w_k  = (const float*)d_in[9];
    const float* w_v  = (const float*)d_in[10];
    const float* w_g  = (const float*)d_in[11];
    const float* b_g  = (const float*)d_in[12];
    const float* w_o  = (const float*)d_in[13];
    const float* b_o  = (const float*)d_in[14];
    float* out = (float*)d_out;

    ln_a_kernel<<<N_TOK, 256>>>(a, g_a, b_a);

    qkvg_proj_kernel<<<dim3(HDM / 64, N_TOK / 64, 4), 256>>>(w_q, w_k, w_v, w_g, b_g);

    pair_bias_kernel<<<dim3(N_TOK / 64, N_TOK), 256>>>(z, g_z, b_z, w_z, mask);

    flash_kernel<<<dim3(N_TOK / 64, NH, KSPLIT), 256>>>();
    combine_kernel<<<(NH * N_TOK * HD) / 256, 256>>>();

    out_proj_kernel<<<dim3(CQ / 64, N_TOK / 32), 256>>>(w_o, b_o, out);
}

// round 7
// speedup vs baseline: 1.8245x; 1.0009x over previous
#include <cuda_runtime.h>
#include <math.h>

#define N_TOK 1024
#define CQ    768
#define CZ    128
#define NH    16
#define HD    48
#define HDM   (NH*HD)              // 768
#define NN    ((size_t)N_TOK*(size_t)N_TOK)
#define KSPLIT 4

// ---------------- scratch (device globals: no allocation allowed) ----------
__device__ float d_an[N_TOK*CQ];                    // LayerNorm(a)
__device__ float d_qkvg[(size_t)N_TOK*4*HDM];       // [tok][q|k|v|g]
__device__ float d_pb[16ULL*1024ULL*1024ULL];       // pair bias (+mask bias)
__device__ float d_og[N_TOK*HDM];                   // gated attention output
__device__ float d_ospl[(size_t)KSPLIT*NH*N_TOK*HD];// split-k partial o (unnormalized)
__device__ float d_ml[(size_t)KSPLIT*NH*N_TOK*2];   // split-k partial (m, l)

// ---------------- f32x2 packed FMA (Blackwell FFMA2, PTX-only) -------------
__device__ __forceinline__ float2 ffma2(float2 a, float2 b, float2 c) {
    float2 d;
    asm("fma.rn.f32x2 %0, %1, %2, %3;"
        : "=l"(reinterpret_cast<unsigned long long&>(d))
        : "l"(reinterpret_cast<unsigned long long&>(a)),
          "l"(reinterpret_cast<unsigned long long&>(b)),
          "l"(reinterpret_cast<unsigned long long&>(c)));
    return d;
}
__device__ __forceinline__ float2 f2b(float x) { return make_float2(x, x); }

// ---------------- 1) LayerNorm over a: [1024][768] -------------------------
__global__ void ln_a_kernel(const float* __restrict__ a, const float* __restrict__ g,
                            const float* __restrict__ b) {
    int row = blockIdx.x, tid = threadIdx.x;
    const float* x = a + (size_t)row * CQ;
    float v0 = x[tid], v1 = x[tid + 256], v2 = x[tid + 512];
    float s = v0 + v1 + v2;
    float s2 = v0 * v0 + v1 * v1 + v2 * v2;
#pragma unroll
    for (int o = 16; o; o >>= 1) {
        s  += __shfl_xor_sync(0xffffffffu, s, o);
        s2 += __shfl_xor_sync(0xffffffffu, s2, o);
    }
    __shared__ float rs[8], rs2[8], bc[2];
    int w = tid >> 5;
    if ((tid & 31) == 0) { rs[w] = s; rs2[w] = s2; }
    __syncthreads();
    if (tid == 0) {
        float S = 0.f, S2 = 0.f;
        for (int i = 0; i < 8; i++) { S += rs[i]; S2 += rs2[i]; }
        float mu = S * (1.f / 768.f);
        float var = S2 * (1.f / 768.f) - mu * mu;
        bc[0] = mu; bc[1] = rsqrtf(var + 1e-5f);
    }
    __syncthreads();
    float mu = bc[0], rstd = bc[1];
    float* o = d_an + (size_t)row * CQ;
    o[tid]       = (v0 - mu) * rstd * g[tid]       + b[tid];
    o[tid + 256] = (v1 - mu) * rstd * g[tid + 256] + b[tid + 256];
    o[tid + 512] = (v2 - mu) * rstd * g[tid + 512] + b[tid + 512];
}

// ---------------- 2) fused q/k/v/g projections (grid.z selects weight) -----
__global__ void qkvg_proj_kernel(const float* __restrict__ wq, const float* __restrict__ wk,
                                 const float* __restrict__ wv, const float* __restrict__ wg,
                                 const float* __restrict__ bg) {
    __shared__ float As[16][68];
    __shared__ float Bs[16][64];
    const int K = CQ, N = HDM, ldc = 4 * HDM;
    int sel = blockIdx.z;
    const float* W = (sel == 0) ? wq : (sel == 1) ? wk : (sel == 2) ? wv : wg;
    int tid = threadIdx.x;
    int m_blk = blockIdx.y * 64, n_blk = blockIdx.x * 64;
    int tx = tid & 15, ty = tid >> 4;
    int ar = tid >> 2, ac4 = tid & 3;
    int br = tid >> 4, bc4 = tid & 15;
    const float* Ap = d_an + (size_t)(m_blk + ar) * K + ac4 * 4;
    const float* Wp = W + (size_t)br * N + n_blk + bc4 * 4;
    float2 acc[4][2];
#pragma unroll
    for (int i = 0; i < 4; i++) { acc[i][0] = make_float2(0.f, 0.f); acc[i][1] = make_float2(0.f, 0.f); }
    for (int k0 = 0; k0 < K; k0 += 16) {
        float4 av = *(const float4*)(Ap + k0);
        float4 bv = *(const float4*)(Wp + (size_t)k0 * N);
        __syncthreads();
        As[ac4 * 4 + 0][ar] = av.x; As[ac4 * 4 + 1][ar] = av.y;
        As[ac4 * 4 + 2][ar] = av.z; As[ac4 * 4 + 3][ar] = av.w;
        *(float4*)&Bs[br][bc4 * 4] = bv;
        __syncthreads();
#pragma unroll
        for (int kk = 0; kk < 16; ++kk) {
            float4 a4 = *(const float4*)&As[kk][ty * 4];
            float4 b4 = *(const float4*)&Bs[kk][tx * 4];
            float2 b01 = make_float2(b4.x, b4.y), b23 = make_float2(b4.z, b4.w);
            acc[0][0] = ffma2(f2b(a4.x), b01, acc[0][0]); acc[0][1] = ffma2(f2b(a4.x), b23, acc[0][1]);
            acc[1][0] = ffma2(f2b(a4.y), b01, acc[1][0]); acc[1][1] = ffma2(f2b(a4.y), b23, acc[1][1]);
            acc[2][0] = ffma2(f2b(a4.z), b01, acc[2][0]); acc[2][1] = ffma2(f2b(a4.z), b23, acc[2][1]);
            acc[3][0] = ffma2(f2b(a4.w), b01, acc[3][0]); acc[3][1] = ffma2(f2b(a4.w), b23, acc[3][1]);
        }
    }
    const float qscale = 0.14433756729740643f;  // 1/sqrt(48)
#pragma unroll
    for (int i = 0; i < 4; i++) {
        int m = m_blk + ty * 4 + i;
        float vals[4] = { acc[i][0].x, acc[i][0].y, acc[i][1].x, acc[i][1].y };
        float4 o;
#pragma unroll
        for (int jn = 0; jn < 4; jn++) {
            int n = n_blk + tx * 4 + jn;
            float v = vals[jn];
            if (sel == 0) v *= qscale;
            else if (sel == 3) v = 1.f / (1.f + __expf(-(v + bg[n])));
            ((float*)&o)[jn] = v;
        }
        *(float4*)(d_qkvg + (size_t)m * ldc + sel * 768 + n_blk + tx * 4) = o;
    }
}

// ---------------- 3) pair bias: fused LN(z) + zn@w_z + mask bias -----------
// block: fixed i, 64 j rows. pb[h][i][j]. Conflict-free wt (stride 130 pairs).
__global__ void __launch_bounds__(256) pair_bias_kernel(
        const float* __restrict__ z, const float* __restrict__ gz,
        const float* __restrict__ bz, const float* __restrict__ wz,
        const float* __restrict__ mask) {
    __shared__ float zs[64][132];      // normalized z rows (also reused as stage)
    __shared__ float2 wt[8][130];      // w_z head-pair packed, padded stride
    int i = blockIdx.y;
    int j0 = blockIdx.x * 64;
    int tid = threadIdx.x;
    int warp = tid >> 5, lane = tid & 31;

    for (int idx = tid; idx < 1024; idx += 256) {
        int c = idx & 127, hp = idx >> 7;
        wt[hp][c] = make_float2(wz[c * 16 + 2 * hp], wz[c * 16 + 2 * hp + 1]);
    }
    float4 gq = *(const float4*)(gz + lane * 4);
    float4 bq = *(const float4*)(bz + lane * 4);

    // LN: 8 rows per warp
#pragma unroll
    for (int rr = 0; rr < 8; ++rr) {
        int r = warp * 8 + rr;
        const float4 v = *(const float4*)(z + ((size_t)i * N_TOK + (j0 + r)) * CZ + lane * 4);
        float s  = v.x + v.y + v.z + v.w;
        float s2 = v.x * v.x + v.y * v.y + v.z * v.z + v.w * v.w;
#pragma unroll
        for (int o = 16; o; o >>= 1) {
            s  += __shfl_xor_sync(0xffffffffu, s, o);
            s2 += __shfl_xor_sync(0xffffffffu, s2, o);
        }
        float mu = s * (1.f / 128.f);
        float var = s2 * (1.f / 128.f) - mu * mu;
        float rstd = rsqrtf(var + 1e-5f);
        float4 o4;
        o4.x = (v.x - mu) * rstd * gq.x + bq.x;
        o4.y = (v.y - mu) * rstd * gq.y + bq.y;
        o4.z = (v.z - mu) * rstd * gq.z + bq.z;
        o4.w = (v.w - mu) * rstd * gq.w + bq.w;
        *(float4*)&zs[r][lane * 4] = o4;
    }
    __syncthreads();

    // GEMM: thread owns rows (jg*2, jg*2+1) x head-pair hp
    int jg = tid >> 3, hp = tid & 7;
    int ja = jg * 2, jb = ja + 1;
    float2 accA = make_float2(0.f, 0.f), accB = accA;
#pragma unroll
    for (int c = 0; c < 128; c += 4) {
        float4 w01 = *(const float4*)&wt[hp][c];      // pairs for c, c+1
        float4 w23 = *(const float4*)&wt[hp][c + 2];  // pairs for c+2, c+3
        float4 za = *(const float4*)&zs[ja][c];
        float4 zb = *(const float4*)&zs[jb][c];
        float2 wA = make_float2(w01.x, w01.y), wB = make_float2(w01.z, w01.w);
        float2 wC = make_float2(w23.x, w23.y), wD = make_float2(w23.z, w23.w);
        accA = ffma2(f2b(za.x), wA, accA); accA = ffma2(f2b(za.y), wB, accA);
        accA = ffma2(f2b(za.z), wC, accA); accA = ffma2(f2b(za.w), wD, accA);
        accB = ffma2(f2b(zb.x), wA, accB); accB = ffma2(f2b(zb.y), wB, accB);
        accB = ffma2(f2b(zb.z), wC, accB); accB = ffma2(f2b(zb.w), wD, accB);
    }
    __syncthreads();          // done reading zs; reuse as stage [16][66]
    float* stage = &zs[0][0];
    stage[(2 * hp) * 66 + ja]     = accA.x;
    stage[(2 * hp + 1) * 66 + ja] = accA.y;
    stage[(2 * hp) * 66 + jb]     = accB.x;
    stage[(2 * hp + 1) * 66 + jb] = accB.y;
    __syncthreads();
    // coalesced output: thread -> (h = tid>>4, j4 = (tid&15)*4)
    int h = tid >> 4, j4 = (tid & 15) * 4;
    float mi = mask[i];
    float4 mj = *(const float4*)(mask + j0 + j4);
    float4 o;
    o.x = stage[h * 66 + j4 + 0] + 1.0e9f * (mi * mj.x - 1.0f);
    o.y = stage[h * 66 + j4 + 1] + 1.0e9f * (mi * mj.y - 1.0f);
    o.z = stage[h * 66 + j4 + 2] + 1.0e9f * (mi * mj.z - 1.0f);
    o.w = stage[h * 66 + j4 + 3] + 1.0e9f * (mi * mj.w - 1.0f);
    *(float4*)(d_pb + (size_t)h * NN + (size_t)i * N_TOK + j0 + j4) = o;
}

// ---------------- 4) split-k flash attention ------------------------------
// grid (16 q-tiles, 16 heads, KSPLIT). Partial (o, m, l) per split.
__global__ void __launch_bounds__(256) flash_kernel() {
    __shared__ float qs[48][68];
    __shared__ float ks[48][64];
    __shared__ float vs[64][48];
    __shared__ float ps[64][68];
    int q0 = blockIdx.x * 64, h = blockIdx.y, split = blockIdx.z;
    int tid = threadIdx.x;
    int qp = tid >> 3, dg = tid & 7;
    int rA = qp, rB = qp + 32;
    int d0 = dg * 6;

    for (int idx = tid; idx < 64 * 12; idx += 256) {
        int r = idx / 12, c4 = idx % 12;
        float4 v = *(const float4*)(d_qkvg + (size_t)(q0 + r) * 3072 + h * 48 + c4 * 4);
        qs[c4 * 4 + 0][r] = v.x; qs[c4 * 4 + 1][r] = v.y;
        qs[c4 * 4 + 2][r] = v.z; qs[c4 * 4 + 3][r] = v.w;
    }

    float2 oA0 = make_float2(0.f, 0.f), oA1 = oA0, oA2 = oA0;
    float2 oB0 = oA0, oB1 = oA0, oB2 = oA0;
    float mA = -1e30f, lA = 0.f, mB = -1e30f, lB = 0.f;

    int kbeg = split * (N_TOK / KSPLIT), kend = kbeg + (N_TOK / KSPLIT);
    for (int k0 = kbeg; k0 < kend; k0 += 64) {
        __syncthreads();
        for (int idx = tid; idx < 64 * 12; idx += 256) {
            int r = idx / 12, c4 = idx % 12;
            float4 kv = *(const float4*)(d_qkvg + (size_t)(k0 + r) * 3072 + 768 + h * 48 + c4 * 4);
            ks[c4 * 4 + 0][r] = kv.x; ks[c4 * 4 + 1][r] = kv.y;
            ks[c4 * 4 + 2][r] = kv.z; ks[c4 * 4 + 3][r] = kv.w;
            *(float4*)&vs[r][c4 * 4] =
                *(const float4*)(d_qkvg + (size_t)(k0 + r) * 3072 + 1536 + h * 48 + c4 * 4);
        }
        size_t pbase = (size_t)h * NN + (size_t)q0 * N_TOK + k0 + dg * 8;
        float4 pA0 = *(const float4*)(d_pb + pbase + (size_t)rA * N_TOK);
        float4 pA1 = *(const float4*)(d_pb + pbase + (size_t)rA * N_TOK + 4);
        float4 pB0 = *(const float4*)(d_pb + pbase + (size_t)rB * N_TOK);
        float4 pB1 = *(const float4*)(d_pb + pbase + (size_t)rB * N_TOK + 4);
        __syncthreads();

        float2 sA[4] = { make_float2(pA0.x, pA0.y), make_float2(pA0.z, pA0.w),
                         make_float2(pA1.x, pA1.y), make_float2(pA1.z, pA1.w) };
        float2 sB[4] = { make_float2(pB0.x, pB0.y), make_float2(pB0.z, pB0.w),
                         make_float2(pB1.x, pB1.y), make_float2(pB1.z, pB1.w) };
#pragma unroll 12
        for (int d = 0; d < 48; ++d) {
            float4 ka = *(const float4*)&ks[d][dg * 8];
            float4 kb = *(const float4*)&ks[d][dg * 8 + 4];
            float2 k01 = make_float2(ka.x, ka.y), k23 = make_float2(ka.z, ka.w);
            float2 k45 = make_float2(kb.x, kb.y), k67 = make_float2(kb.z, kb.w);
            float2 qa = f2b(qs[d][rA]);
            float2 qb = f2b(qs[d][rB]);
            sA[0] = ffma2(qa, k01, sA[0]); sA[1] = ffma2(qa, k23, sA[1]);
            sA[2] = ffma2(qa, k45, sA[2]); sA[3] = ffma2(qa, k67, sA[3]);
            sB[0] = ffma2(qb, k01, sB[0]); sB[1] = ffma2(qb, k23, sB[1]);
            sB[2] = ffma2(qb, k45, sB[2]); sB[3] = ffma2(qb, k67, sB[3]);
        }
        float tmA = fmaxf(fmaxf(fmaxf(sA[0].x, sA[0].y), fmaxf(sA[1].x, sA[1].y)),
                          fmaxf(fmaxf(sA[2].x, sA[2].y), fmaxf(sA[3].x, sA[3].y)));
        float tmB = fmaxf(fmaxf(fmaxf(sB[0].x, sB[0].y), fmaxf(sB[1].x, sB[1].y)),
                          fmaxf(fmaxf(sB[2].x, sB[2].y), fmaxf(sB[3].x, sB[3].y)));
#pragma unroll
        for (int o = 1; o < 8; o <<= 1) {
            tmA = fmaxf(tmA, __shfl_xor_sync(0xffffffffu, tmA, o));
            tmB = fmaxf(tmB, __shfl_xor_sync(0xffffffffu, tmB, o));
        }
        float mAn = fmaxf(mA, tmA), mBn = fmaxf(mB, tmB);
        float scA = __expf(mA - mAn), scB = __expf(mB - mBn);
        float sumA = 0.f, sumB = 0.f;
#pragma unroll
        for (int jj = 0; jj < 4; ++jj) {
            float2 eA, eB;
            eA.x = __expf(sA[jj].x - mAn); eA.y = __expf(sA[jj].y - mAn);
            eB.x = __expf(sB[jj].x - mBn); eB.y = __expf(sB[jj].y - mBn);
            sumA += eA.x + eA.y; sumB += eB.x + eB.y;
            *(float2*)&ps[rA][dg * 8 + jj * 2] = eA;
            *(float2*)&ps[rB][dg * 8 + jj * 2] = eB;
        }
#pragma unroll
        for (int o = 1; o < 8; o <<= 1) {
            sumA += __shfl_xor_sync(0xffffffffu, sumA, o);
            sumB += __shfl_xor_sync(0xffffffffu, sumB, o);
        }
        lA = lA * scA + sumA; mA = mAn;
        lB = lB * scB + sumB; mB = mBn;
        oA0.x *= scA; oA0.y *= scA; oA1.x *= scA; oA1.y *= scA; oA2.x *= scA; oA2.y *= scA;
        oB0.x *= scB; oB0.y *= scB; oB1.x *= scB; oB1.y *= scB; oB2.x *= scB; oB2.y *= scB;
        __syncthreads();
#pragma unroll 16
        for (int kk = 0; kk < 64; ++kk) {
            float2 v01 = *(const float2*)&vs[kk][d0];
            float2 v23 = *(const float2*)&vs[kk][d0 + 2];
            float2 v45 = *(const float2*)&vs[kk][d0 + 4];
            float2 pa = f2b(ps[rA][kk]);
            float2 pbv = f2b(ps[rB][kk]);
            oA0 = ffma2(pa, v01, oA0); oA1 = ffma2(pa, v23, oA1); oA2 = ffma2(pa, v45, oA2);
            oB0 = ffma2(pbv, v01, oB0); oB1 = ffma2(pbv, v23, oB1); oB2 = ffma2(pbv, v45, oB2);
        }
    }
    // store unnormalized partials
    size_t obase = ((size_t)split * NH + h) * N_TOK;
    float* opA = d_ospl + (obase + q0 + rA) * HD + d0;
    float* opB = d_ospl + (obase + q0 + rB) * HD + d0;
    opA[0] = oA0.x; opA[1] = oA0.y; opA[2] = oA1.x;
    opA[3] = oA1.y; opA[4] = oA2.x; opA[5] = oA2.y;
    opB[0] = oB0.x; opB[1] = oB0.y; opB[2] = oB1.x;
    opB[3] = oB1.y; opB[4] = oB2.x; opB[5] = oB2.y;
    if (dg == 0) {
        d_ml[(obase + q0 + rA) * 2]     = mA;
        d_ml[(obase + q0 + rA) * 2 + 1] = lA;
        d_ml[(obase + q0 + rB) * 2]     = mB;
        d_ml[(obase + q0 + rB) * 2 + 1] = lB;
    }
}

// ---------------- 4b) combine splits + gate --------------------------------
__global__ void combine_kernel() {
    int idx = blockIdx.x * 256 + threadIdx.x;        // 16*1024*48
    int d = idx % HD;
    int hq = idx / HD;
    int q = hq & (N_TOK - 1);
    int h = hq >> 10;
    size_t row = (size_t)h * N_TOK + q;
    float m[KSPLIT], l[KSPLIT];
    float mx = -1e30f;
#pragma unroll
    for (int s = 0; s < KSPLIT; ++s) {
        m[s] = d_ml[((size_t)s * NH * N_TOK + row) * 2];
        l[s] = d_ml[((size_t)s * NH * N_TOK + row) * 2 + 1];
        mx = fmaxf(mx, m[s]);
    }
    float lt = 0.f, ov = 0.f;
#pragma unroll
    for (int s = 0; s < KSPLIT; ++s) {
        float w = __expf(m[s] - mx);
        lt += l[s] * w;
        ov += d_ospl[((size_t)s * NH * N_TOK + row) * HD + d] * w;
    }
    float g = d_qkvg[(size_t)q * 3072 + 2304 + h * 48 + d];
    d_og[(size_t)q * HDM + h * 48 + d] = ov / lt * g;
}

// ---------------- 5) output projection: og @ w_o + b_o (32x64 tiles) -------
__global__ void out_proj_kernel(const float* __restrict__ W, const float* __restrict__ bias,
                                float* __restrict__ C) {
    __shared__ float As[16][36];
    __shared__ float Bs[16][64];
    const int K = HDM, N = CQ, ldc = CQ;
    int tid = threadIdx.x;
    int m_blk = blockIdx.y * 32, n_blk = blockIdx.x * 64;
    int tx = tid & 15, ty = tid >> 4;
    int ar = tid >> 3, ac2 = tid & 7;
    int br = tid >> 4, bc4 = tid & 15;
    const float* Ap = d_og + (size_t)(m_blk + ar) * K + ac2 * 2;
    const float* Wp = W + (size_t)br * N + n_blk + bc4 * 4;
    float2 acc[2][2];
#pragma unroll
    for (int i = 0; i < 2; i++) { acc[i][0] = make_float2(0.f, 0.f); acc[i][1] = make_float2(0.f, 0.f); }
    for (int k0 = 0; k0 < K; k0 += 16) {
        float2 av = *(const float2*)(Ap + k0);
        float4 bv = *(const float4*)(Wp + (size_t)k0 * N);
        __syncthreads();
        As[ac2 * 2 + 0][ar] = av.x;
        As[ac2 * 2 + 1][ar] = av.y;
        *(float4*)&Bs[br][bc4 * 4] = bv;
        __syncthreads();
#pragma unroll
        for (int kk = 0; kk < 16; ++kk) {
            float2 a2 = *(const float2*)&As[kk][ty * 2];
            float4 b4 = *(const float4*)&Bs[kk][tx * 4];
            float2 b01 = make_float2(b4.x, b4.y), b23 = make_float2(b4.z, b4.w);
            acc[0][0] = ffma2(f2b(a2.x), b01, acc[0][0]); acc[0][1] = ffma2(f2b(a2.x), b23, acc[0][1]);
            acc[1][0] = ffma2(f2b(a2.y), b01, acc[1][0]); acc[1][1] = ffma2(f2b(a2.y), b23, acc[1][1]);
        }
    }
#pragma unroll
    for (int i = 0; i < 2; i++) {
        int m = m_blk + ty * 2 + i;
        float vals[4] = { acc[i][0].x, acc[i][0].y, acc[i][1].x, acc[i][1].y };
        float4 o;
#pragma unroll
        for (int jn = 0; jn < 4; jn++) {
            int n = n_blk + tx * 4 + jn;
            ((float*)&o)[jn] = vals[jn] + bias[n];
        }
        *(float4*)(C + (size_t)m * ldc + n_blk + tx * 4) = o;
    }
}

// ---------------- launch ---------------------------------------------------
extern "C" void kernel_launch(void* const* d_in, const int* in_sizes, int n_in,
                              void* d_out, int out_size) {
    const float* a    = (const float*)d_in[0];
    const float* z    = (const float*)d_in[1];
    const float* mask = (const float*)d_in[2];
    const float* g_a  = (const float*)d_in[3];
    const float* b_a  = (const float*)d_in[4];
    const float* g_z  = (const float*)d_in[5];
    const float* b_z  = (const float*)d_in[6];
    const float* w_z  = (const float*)d_in[7];
    const float* w_q  = (const float*)d_in[8];
    const float* w_k  = (const float*)d_in[9];
    const float* w_v  = (const float*)d_in[10];
    const float* w_g  = (const float*)d_in[11];
    const float* b_g  = (const float*)d_in[12];
    const float* w_o  = (const float*)d_in[13];
    const float* b_o  = (const float*)d_in[14];
    float* out = (float*)d_out;

    ln_a_kernel<<<N_TOK, 256>>>(a, g_a, b_a);

    qkvg_proj_kernel<<<dim3(HDM / 64, N_TOK / 64, 4), 256>>>(w_q, w_k, w_v, w_g, b_g);

    pair_bias_kernel<<<dim3(N_TOK / 64, N_TOK), 256>>>(z, g_z, b_z, w_z, mask);

    flash_kernel<<<dim3(N_TOK / 64, NH, KSPLIT), 256>>>();
    combine_kernel<<<(NH * N_TOK * HD) / 256, 256>>>();

    out_proj_kernel<<<dim3(CQ / 64, N_TOK / 32), 256>>>(w_o, b_o, out);
}

// round 9
// speedup vs baseline: 2.0133x; 1.1035x over previous
#include <cuda_runtime.h>
#include <math.h>

#define N_TOK 1024
#define CQ    768
#define CZ    128
#define NH    16
#define HD    48
#define HDM   (NH*HD)              // 768
#define NN    ((size_t)N_TOK*(size_t)N_TOK)
#define KSPLIT 4

// ---------------- scratch (device globals: no allocation allowed) ----------
__device__ float d_an[N_TOK*CQ];                    // LayerNorm(a)
__device__ float d_qkvg[(size_t)N_TOK*4*HDM];       // [tok][q|k|v|g]
__device__ float d_kT[(size_t)HDM*N_TOK];           // k transposed [hd][tok]
__device__ float d_pb[16ULL*1024ULL*1024ULL];       // pair bias (+mask bias)
__device__ float d_og[N_TOK*HDM];                   // gated attention output
__device__ float d_ospl[(size_t)KSPLIT*NH*N_TOK*HD];// split-k partial o (unnormalized)
__device__ float d_ml[(size_t)KSPLIT*NH*N_TOK*2];   // split-k partial (m, l)

// ---------------- f32x2 packed FMA (Blackwell FFMA2, PTX-only) -------------
__device__ __forceinline__ float2 ffma2(float2 a, float2 b, float2 c) {
    float2 d;
    asm("fma.rn.f32x2 %0, %1, %2, %3;"
        : "=l"(reinterpret_cast<unsigned long long&>(d))
        : "l"(reinterpret_cast<unsigned long long&>(a)),
          "l"(reinterpret_cast<unsigned long long&>(b)),
          "l"(reinterpret_cast<unsigned long long&>(c)));
    return d;
}
__device__ __forceinline__ float2 f2b(float x) { return make_float2(x, x); }

// ---------------- 1) LayerNorm over a: [1024][768] -------------------------
__global__ void ln_a_kernel(const float* __restrict__ a, const float* __restrict__ g,
                            const float* __restrict__ b) {
    int row = blockIdx.x, tid = threadIdx.x;
    const float* x = a + (size_t)row * CQ;
    float v0 = x[tid], v1 = x[tid + 256], v2 = x[tid + 512];
    float s = v0 + v1 + v2;
    float s2 = v0 * v0 + v1 * v1 + v2 * v2;
#pragma unroll
    for (int o = 16; o; o >>= 1) {
        s  += __shfl_xor_sync(0xffffffffu, s, o);
        s2 += __shfl_xor_sync(0xffffffffu, s2, o);
    }
    __shared__ float rs[8], rs2[8], bc[2];
    int w = tid >> 5;
    if ((tid & 31) == 0) { rs[w] = s; rs2[w] = s2; }
    __syncthreads();
    if (tid == 0) {
        float S = 0.f, S2 = 0.f;
        for (int i = 0; i < 8; i++) { S += rs[i]; S2 += rs2[i]; }
        float mu = S * (1.f / 768.f);
        float var = S2 * (1.f / 768.f) - mu * mu;
        bc[0] = mu; bc[1] = rsqrtf(var + 1e-5f);
    }
    __syncthreads();
    float mu = bc[0], rstd = bc[1];
    float* o = d_an + (size_t)row * CQ;
    o[tid]       = (v0 - mu) * rstd * g[tid]       + b[tid];
    o[tid + 256] = (v1 - mu) * rstd * g[tid + 256] + b[tid + 256];
    o[tid + 512] = (v2 - mu) * rstd * g[tid + 512] + b[tid + 512];
}

// ---------------- 2) fused q/k/v/g projections (grid.z selects weight) -----
// sel==1 (k) additionally writes transposed copy to d_kT[hd][tok].
__global__ void qkvg_proj_kernel(const float* __restrict__ wq, const float* __restrict__ wk,
                                 const float* __restrict__ wv, const float* __restrict__ wg,
                                 const float* __restrict__ bg) {
    __shared__ float As[16][68];
    __shared__ float Bs[16][64];
    __shared__ float ts[64][68];   // transpose stage (sel==1 only)
    const int K = CQ, N = HDM, ldc = 4 * HDM;
    int sel = blockIdx.z;
    const float* W = (sel == 0) ? wq : (sel == 1) ? wk : (sel == 2) ? wv : wg;
    int tid = threadIdx.x;
    int m_blk = blockIdx.y * 64, n_blk = blockIdx.x * 64;
    int tx = tid & 15, ty = tid >> 4;
    int ar = tid >> 2, ac4 = tid & 3;
    int br = tid >> 4, bc4 = tid & 15;
    const float* Ap = d_an + (size_t)(m_blk + ar) * K + ac4 * 4;
    const float* Wp = W + (size_t)br * N + n_blk + bc4 * 4;
    float2 acc[4][2];
#pragma unroll
    for (int i = 0; i < 4; i++) { acc[i][0] = make_float2(0.f, 0.f); acc[i][1] = make_float2(0.f, 0.f); }
    for (int k0 = 0; k0 < K; k0 += 16) {
        float4 av = *(const float4*)(Ap + k0);
        float4 bv = *(const float4*)(Wp + (size_t)k0 * N);
        __syncthreads();
        As[ac4 * 4 + 0][ar] = av.x; As[ac4 * 4 + 1][ar] = av.y;
        As[ac4 * 4 + 2][ar] = av.z; As[ac4 * 4 + 3][ar] = av.w;
        *(float4*)&Bs[br][bc4 * 4] = bv;
        __syncthreads();
#pragma unroll
        for (int kk = 0; kk < 16; ++kk) {
            float4 a4 = *(const float4*)&As[kk][ty * 4];
            float4 b4 = *(const float4*)&Bs[kk][tx * 4];
            float2 b01 = make_float2(b4.x, b4.y), b23 = make_float2(b4.z, b4.w);
            acc[0][0] = ffma2(f2b(a4.x), b01, acc[0][0]); acc[0][1] = ffma2(f2b(a4.x), b23, acc[0][1]);
            acc[1][0] = ffma2(f2b(a4.y), b01, acc[1][0]); acc[1][1] = ffma2(f2b(a4.y), b23, acc[1][1]);
            acc[2][0] = ffma2(f2b(a4.z), b01, acc[2][0]); acc[2][1] = ffma2(f2b(a4.z), b23, acc[2][1]);
            acc[3][0] = ffma2(f2b(a4.w), b01, acc[3][0]); acc[3][1] = ffma2(f2b(a4.w), b23, acc[3][1]);
        }
    }
    const float qscale = 0.14433756729740643f;  // 1/sqrt(48)
#pragma unroll
    for (int i = 0; i < 4; i++) {
        int m = m_blk + ty * 4 + i;
        float vals[4] = { acc[i][0].x, acc[i][0].y, acc[i][1].x, acc[i][1].y };
        float4 o;
#pragma unroll
        for (int jn = 0; jn < 4; jn++) {
            int n = n_blk + tx * 4 + jn;
            float v = vals[jn];
            if (sel == 0) v *= qscale;
            else if (sel == 3) v = 1.f / (1.f + __expf(-(v + bg[n])));
            ((float*)&o)[jn] = v;
        }
        *(float4*)(d_qkvg + (size_t)m * ldc + sel * 768 + n_blk + tx * 4) = o;
        if (sel == 1) {
            ts[tx * 4 + 0][ty * 4 + i] = vals[0];
            ts[tx * 4 + 1][ty * 4 + i] = vals[1];
            ts[tx * 4 + 2][ty * 4 + i] = vals[2];
            ts[tx * 4 + 3][ty * 4 + i] = vals[3];
        }
    }
    if (sel == 1) {
        __syncthreads();
        for (int idx = tid; idx < 1024; idx += 256) {
            int n = idx >> 4, m4 = idx & 15;
            *(float4*)(d_kT + (size_t)(n_blk + n) * N_TOK + m_blk + m4 * 4) =
                *(const float4*)&ts[n][m4 * 4];
        }
    }
}

// ---------------- 3) pair bias: fused LN(z) + zn@w_z + mask bias -----------
__global__ void __launch_bounds__(256) pair_bias_kernel(
        const float* __restrict__ z, const float* __restrict__ gz,
        const float* __restrict__ bz, const float* __restrict__ wz,
        const float* __restrict__ mask) {
    __shared__ float zs[64][132];      // normalized z rows (also reused as stage)
    __shared__ float2 wt[8][130];      // w_z head-pair packed, padded stride
    int i = blockIdx.y;
    int j0 = blockIdx.x * 64;
    int tid = threadIdx.x;
    int warp = tid >> 5, lane = tid & 31;

    for (int idx = tid; idx < 1024; idx += 256) {
        int c = idx & 127, hp = idx >> 7;
        wt[hp][c] = make_float2(wz[c * 16 + 2 * hp], wz[c * 16 + 2 * hp + 1]);
    }
    float4 gq = *(const float4*)(gz + lane * 4);
    float4 bq = *(const float4*)(bz + lane * 4);

#pragma unroll
    for (int rr = 0; rr < 8; ++rr) {
        int r = warp * 8 + rr;
        const float4 v = *(const float4*)(z + ((size_t)i * N_TOK + (j0 + r)) * CZ + lane * 4);
        float s  = v.x + v.y + v.z + v.w;
        float s2 = v.x * v.x + v.y * v.y + v.z * v.z + v.w * v.w;
#pragma unroll
        for (int o = 16; o; o >>= 1) {
            s  += __shfl_xor_sync(0xffffffffu, s, o);
            s2 += __shfl_xor_sync(0xffffffffu, s2, o);
        }
        float mu = s * (1.f / 128.f);
        float var = s2 * (1.f / 128.f) - mu * mu;
        float rstd = rsqrtf(var + 1e-5f);
        float4 o4;
        o4.x = (v.x - mu) * rstd * gq.x + bq.x;
        o4.y = (v.y - mu) * rstd * gq.y + bq.y;
        o4.z = (v.z - mu) * rstd * gq.z + bq.z;
        o4.w = (v.w - mu) * rstd * gq.w + bq.w;
        *(float4*)&zs[r][lane * 4] = o4;
    }
    __syncthreads();

    int jg = tid >> 3, hp = tid & 7;
    int ja = jg * 2, jb = ja + 1;
    float2 accA = make_float2(0.f, 0.f), accB = accA;
#pragma unroll
    for (int c = 0; c < 128; c += 4) {
        float4 w01 = *(const float4*)&wt[hp][c];
        float4 w23 = *(const float4*)&wt[hp][c + 2];
        float4 za = *(const float4*)&zs[ja][c];
        float4 zb = *(const float4*)&zs[jb][c];
        float2 wA = make_float2(w01.x, w01.y), wB = make_float2(w01.z, w01.w);
        float2 wC = make_float2(w23.x, w23.y), wD = make_float2(w23.z, w23.w);
        accA = ffma2(f2b(za.x), wA, accA); accA = ffma2(f2b(za.y), wB, accA);
        accA = ffma2(f2b(za.z), wC, accA); accA = ffma2(f2b(za.w), wD, accA);
        accB = ffma2(f2b(zb.x), wA, accB); accB = ffma2(f2b(zb.y), wB, accB);
        accB = ffma2(f2b(zb.z), wC, accB); accB = ffma2(f2b(zb.w), wD, accB);
    }
    __syncthreads();
    float* stage = &zs[0][0];
    stage[(2 * hp) * 66 + ja]     = accA.x;
    stage[(2 * hp + 1) * 66 + ja] = accA.y;
    stage[(2 * hp) * 66 + jb]     = accB.x;
    stage[(2 * hp + 1) * 66 + jb] = accB.y;
    __syncthreads();
    int h = tid >> 4, j4 = (tid & 15) * 4;
    float mi = mask[i];
    float4 mj = *(const float4*)(mask + j0 + j4);
    float4 o;
    o.x = stage[h * 66 + j4 + 0] + 1.0e9f * (mi * mj.x - 1.0f);
    o.y = stage[h * 66 + j4 + 1] + 1.0e9f * (mi * mj.y - 1.0f);
    o.z = stage[h * 66 + j4 + 2] + 1.0e9f * (mi * mj.z - 1.0f);
    o.w = stage[h * 66 + j4 + 3] + 1.0e9f * (mi * mj.w - 1.0f);
    *(float4*)(d_pb + (size_t)h * NN + (size_t)i * N_TOK + j0 + j4) = o;
}

// ---------------- 4) split-k flash attention ------------------------------
// QK/softmax mapping: (qg = tid>>4, dg = tid&15) -> 4 rows {qg+16i} x 4 cols.
// PV mapping: (qp = tid>>3, dg8 = tid&7) -> 2 rows {qp, qp+32} x 6 cols.
__global__ void __launch_bounds__(256) flash_kernel() {
    __shared__ float qs[64][48];     // [q][d] — no transpose needed
    __shared__ float ks[48][64];     // [d][k] — from d_kT, conflict-free
    __shared__ float vs[64][48];     // [k][d]
    __shared__ float ps[64][68];     // probs
    __shared__ float sc[64];         // per-row rescale for this tile
    int q0 = blockIdx.x * 64, h = blockIdx.y, split = blockIdx.z;
    int tid = threadIdx.x;
    int qg = tid >> 4, dg = tid & 15;
    int qp = tid >> 3, dg8 = tid & 7, d0 = dg8 * 6;

    for (int idx = tid; idx < 64 * 12; idx += 256) {
        int r = idx / 12, c4 = idx % 12;
        *(float4*)&qs[r][c4 * 4] =
            *(const float4*)(d_qkvg + (size_t)(q0 + r) * 3072 + h * 48 + c4 * 4);
    }

    float2 oA0 = make_float2(0.f, 0.f), oA1 = oA0, oA2 = oA0;
    float2 oB0 = oA0, oB1 = oA0, oB2 = oA0;
    float m[4], l[4];
#pragma unroll
    for (int i = 0; i < 4; i++) { m[i] = -1e30f; l[i] = 0.f; }

    int kbeg = split * (N_TOK / KSPLIT), kend = kbeg + (N_TOK / KSPLIT);
    for (int k0 = kbeg; k0 < kend; k0 += 64) {
        __syncthreads();   // prev PV done
        for (int idx = tid; idx < 48 * 16; idx += 256) {
            int d = idx >> 4, c = idx & 15;
            *(float4*)&ks[d][c * 4] =
                *(const float4*)(d_kT + (size_t)(h * 48 + d) * N_TOK + k0 + c * 4);
        }
        for (int idx = tid; idx < 64 * 12; idx += 256) {
            int r = idx / 12, c4 = idx % 12;
            *(float4*)&vs[r][c4 * 4] =
                *(const float4*)(d_qkvg + (size_t)(k0 + r) * 3072 + 1536 + h * 48 + c4 * 4);
        }
        float2 s[4][2];
#pragma unroll
        for (int i = 0; i < 4; i++) {
            float4 p = *(const float4*)(d_pb + (size_t)h * NN +
                                        (size_t)(q0 + qg + 16 * i) * N_TOK + k0 + dg * 4);
            s[i][0] = make_float2(p.x, p.y); s[i][1] = make_float2(p.z, p.w);
        }
        __syncthreads();   // tiles staged

#pragma unroll 8
        for (int d = 0; d < 48; ++d) {
            float4 kv = *(const float4*)&ks[d][dg * 4];
            float2 k01 = make_float2(kv.x, kv.y), k23 = make_float2(kv.z, kv.w);
#pragma unroll
            for (int i = 0; i < 4; i++) {
                float2 q = f2b(qs[qg + 16 * i][d]);
                s[i][0] = ffma2(q, k01, s[i][0]);
                s[i][1] = ffma2(q, k23, s[i][1]);
            }
        }
        // online softmax per row (reduce over 16 dg lanes)
#pragma unroll
        for (int i = 0; i < 4; i++) {
            float tm = fmaxf(fmaxf(s[i][0].x, s[i][0].y), fmaxf(s[i][1].x, s[i][1].y));
#pragma unroll
            for (int o = 1; o < 16; o <<= 1) tm = fmaxf(tm, __shfl_xor_sync(0xffffffffu, tm, o));
            float mn = fmaxf(m[i], tm);
            float scl = __expf(m[i] - mn);
            float2 e0, e1;
            e0.x = __expf(s[i][0].x - mn); e0.y = __expf(s[i][0].y - mn);
            e1.x = __expf(s[i][1].x - mn); e1.y = __expf(s[i][1].y - mn);
            float sum = e0.x + e0.y + e1.x + e1.y;
#pragma unroll
            for (int o = 1; o < 16; o <<= 1) sum += __shfl_xor_sync(0xffffffffu, sum, o);
            l[i] = l[i] * scl + sum;
            m[i] = mn;
            *(float2*)&ps[qg + 16 * i][dg * 4] = e0;
            *(float2*)&ps[qg + 16 * i][dg * 4 + 2] = e1;
            if (dg == 0) sc[qg + 16 * i] = scl;
        }
        __syncthreads();   // ps, sc ready

        float sA = sc[qp], sB = sc[qp + 32];
        oA0.x *= sA; oA0.y *= sA; oA1.x *= sA; oA1.y *= sA; oA2.x *= sA; oA2.y *= sA;
        oB0.x *= sB; oB0.y *= sB; oB1.x *= sB; oB1.y *= sB; oB2.x *= sB; oB2.y *= sB;
#pragma unroll 16
        for (int kk = 0; kk < 64; ++kk) {
            float2 v01 = *(const float2*)&vs[kk][d0];
            float2 v23 = *(const float2*)&vs[kk][d0 + 2];
            float2 v45 = *(const float2*)&vs[kk][d0 + 4];
            float2 pa = f2b(ps[qp][kk]);
            float2 pb2 = f2b(ps[qp + 32][kk]);
            oA0 = ffma2(pa, v01, oA0); oA1 = ffma2(pa, v23, oA1); oA2 = ffma2(pa, v45, oA2);
            oB0 = ffma2(pb2, v01, oB0); oB1 = ffma2(pb2, v23, oB1); oB2 = ffma2(pb2, v45, oB2);
        }
    }
    // store unnormalized partials
    size_t obase = ((size_t)split * NH + h) * N_TOK;
    float* opA = d_ospl + (obase + q0 + qp) * HD + d0;
    float* opB = d_ospl + (obase + q0 + qp + 32) * HD + d0;
    opA[0] = oA0.x; opA[1] = oA0.y; opA[2] = oA1.x;
    opA[3] = oA1.y; opA[4] = oA2.x; opA[5] = oA2.y;
    opB[0] = oB0.x; opB[1] = oB0.y; opB[2] = oB1.x;
    opB[3] = oB1.y; opB[4] = oB2.x; opB[5] = oB2.y;
    if (dg == 0) {
#pragma unroll
        for (int i = 0; i < 4; i++) {
            d_ml[(obase + q0 + qg + 16 * i) * 2]     = m[i];
            d_ml[(obase + q0 + qg + 16 * i) * 2 + 1] = l[i];
        }
    }
}

// ---------------- 4b) combine splits + gate --------------------------------
__global__ void combine_kernel() {
    int idx = blockIdx.x * 256 + threadIdx.x;        // 16*1024*48
    int d = idx % HD;
    int hq = idx / HD;
    int q = hq & (N_TOK - 1);
    int h = hq >> 10;
    size_t row = (size_t)h * N_TOK + q;
    float m[KSPLIT], l[KSPLIT];
    float mx = -1e30f;
#pragma unroll
    for (int s = 0; s < KSPLIT; ++s) {
        m[s] = d_ml[((size_t)s * NH * N_TOK + row) * 2];
        l[s] = d_ml[((size_t)s * NH * N_TOK + row) * 2 + 1];
        mx = fmaxf(mx, m[s]);
    }
    float lt = 0.f, ov = 0.f;
#pragma unroll
    for (int s = 0; s < KSPLIT; ++s) {
        float w = __expf(m[s] - mx);
        lt += l[s] * w;
        ov += d_ospl[((size_t)s * NH * N_TOK + row) * HD + d] * w;
    }
    float g = d_qkvg[(size_t)q * 3072 + 2304 + h * 48 + d];
    d_og[(size_t)q * HDM + h * 48 + d] = ov / lt * g;
}

// ---------------- 5) output projection: og @ w_o + b_o (32x64 tiles) -------
__global__ void out_proj_kernel(const float* __restrict__ W, const float* __restrict__ bias,
                                float* __restrict__ C) {
    __shared__ float As[16][36];
    __shared__ float Bs[16][64];
    const int K = HDM, N = CQ, ldc = CQ;
    int tid = threadIdx.x;
    int m_blk = blockIdx.y * 32, n_blk = blockIdx.x * 64;
    int tx = tid & 15, ty = tid >> 4;
    int ar = tid >> 3, ac2 = tid & 7;
    int br = tid >> 4, bc4 = tid & 15;
    const float* Ap = d_og + (size_t)(m_blk + ar) * K + ac2 * 2;
    const float* Wp = W + (size_t)br * N + n_blk + bc4 * 4;
    float2 acc[2][2];
#pragma unroll
    for (int i = 0; i < 2; i++) { acc[i][0] = make_float2(0.f, 0.f); acc[i][1] = make_float2(0.f, 0.f); }
    for (int k0 = 0; k0 < K; k0 += 16) {
        float2 av = *(const float2*)(Ap + k0);
        float4 bv = *(const float4*)(Wp + (size_t)k0 * N);
        __syncthreads();
        As[ac2 * 2 + 0][ar] = av.x;
        As[ac2 * 2 + 1][ar] = av.y;
        *(float4*)&Bs[br][bc4 * 4] = bv;
        __syncthreads();
#pragma unroll
        for (int kk = 0; kk < 16; ++kk) {
            float2 a2 = *(const float2*)&As[kk][ty * 2];
            float4 b4 = *(const float4*)&Bs[kk][tx * 4];
            float2 b01 = make_float2(b4.x, b4.y), b23 = make_float2(b4.z, b4.w);
            acc[0][0] = ffma2(f2b(a2.x), b01, acc[0][0]); acc[0][1] = ffma2(f2b(a2.x), b23, acc[0][1]);
            acc[1][0] = ffma2(f2b(a2.y), b01, acc[1][0]); acc[1][1] = ffma2(f2b(a2.y), b23, acc[1][1]);
        }
    }
#pragma unroll
    for (int i = 0; i < 2; i++) {
        int m = m_blk + ty * 2 + i;
        float vals[4] = { acc[i][0].x, acc[i][0].y, acc[i][1].x, acc[i][1].y };
        float4 o;
#pragma unroll
        for (int jn = 0; jn < 4; jn++) {
            int n = n_blk + tx * 4 + jn;
            ((float*)&o)[jn] = vals[jn] + bias[n];
        }
        *(float4*)(C + (size_t)m * ldc + n_blk + tx * 4) = o;
    }
}

// ---------------- launch ---------------------------------------------------
extern "C" void kernel_launch(void* const* d_in, const int* in_sizes, int n_in,
                              void* d_out, int out_size) {
    const float* a    = (const float*)d_in[0];
    const float* z    = (const float*)d_in[1];
    const float* mask = (const float*)d_in[2];
    const float* g_a  = (const float*)d_in[3];
    const float* b_a  = (const float*)d_in[4];
    const float* g_z  = (const float*)d_in[5];
    const float* b_z  = (const float*)d_in[6];
    const float* w_z  = (const float*)d_in[7];
    const float* w_q  = (const float*)d_in[8];
    const float* w_k  = (const float*)d_in[9];
    const float* w_v  = (const float*)d_in[10];
    const float* w_g  = (const float*)d_in[11];
    const float* b_g  = (const float*)d_in[12];
    const float* w_o  = (const float*)d_in[13];
    const float* b_o  = (const float*)d_in[14];
    float* out = (float*)d_out;

    ln_a_kernel<<<N_TOK, 256>>>(a, g_a, b_a);

    qkvg_proj_kernel<<<dim3(HDM / 64, N_TOK / 64, 4), 256>>>(w_q, w_k, w_v, w_g, b_g);

    pair_bias_kernel<<<dim3(N_TOK / 64, N_TOK), 256>>>(z, g_z, b_z, w_z, mask);

    flash_kernel<<<dim3(N_TOK / 64, NH, KSPLIT), 256>>>();
    combine_kernel<<<(NH * N_TOK * HD) / 256, 256>>>();

    out_proj_kernel<<<dim3(CQ / 64, N_TOK / 32), 256>>>(w_o, b_o, out);
}

// round 10
// speedup vs baseline: 2.1594x; 1.0726x over previous
#include <cuda_runtime.h>
#include <math.h>

#define N_TOK 1024
#define CQ    768
#define CZ    128
#define NH    16
#define HD    48
#define HDM   (NH*HD)              // 768
#define NN    ((size_t)N_TOK*(size_t)N_TOK)
#define KSPLIT 4

// ---------------- scratch (device globals: no allocation allowed) ----------
__device__ float d_an[N_TOK*CQ];                    // LayerNorm(a)
__device__ float d_qkvg[(size_t)N_TOK*4*HDM];       // [tok][q|k|v|g]
__device__ float d_kT[(size_t)HDM*N_TOK];           // k transposed [hd][tok]
__device__ float d_pb[16ULL*1024ULL*1024ULL];       // pair bias (+mask bias)
__device__ float d_og[N_TOK*HDM];                   // gated attention output
__device__ float d_ospl[(size_t)KSPLIT*NH*N_TOK*HD];// split-k partial o (unnormalized)
__device__ float d_ml[(size_t)KSPLIT*NH*N_TOK*2];   // split-k partial (m, l)
__device__ float2 d_gwT[8*130];                     // (g*w_z) head-pair packed, padded
__device__ float2 d_G2[8];                          // G_h = sum_c g_c w_ch (pairs)
__device__ float2 d_B2[8];                          // B_h = sum_c b_c w_ch (pairs)

// ---------------- f32x2 packed FMA (Blackwell FFMA2, PTX-only) -------------
__device__ __forceinline__ float2 ffma2(float2 a, float2 b, float2 c) {
    float2 d;
    asm("fma.rn.f32x2 %0, %1, %2, %3;"
        : "=l"(reinterpret_cast<unsigned long long&>(d))
        : "l"(reinterpret_cast<unsigned long long&>(a)),
          "l"(reinterpret_cast<unsigned long long&>(b)),
          "l"(reinterpret_cast<unsigned long long&>(c)));
    return d;
}
__device__ __forceinline__ float2 f2b(float x) { return make_float2(x, x); }

// ---------------- 0) setup: gw = g.*w_z (transposed+packed), G, B ----------
__global__ void setup_kernel(const float* __restrict__ gz, const float* __restrict__ bz,
                             const float* __restrict__ wz) {
    int tid = threadIdx.x;  // 256
    for (int idx = tid; idx < 1024; idx += 256) {
        int hp = idx >> 7, c = idx & 127;
        float g = gz[c];
        d_gwT[hp * 130 + c] = make_float2(g * wz[c * 16 + 2 * hp],
                                          g * wz[c * 16 + 2 * hp + 1]);
    }
    if (tid < 8) {
        float2 G = make_float2(0.f, 0.f), B = make_float2(0.f, 0.f);
        for (int c = 0; c < 128; ++c) {
            float w0 = wz[c * 16 + 2 * tid], w1 = wz[c * 16 + 2 * tid + 1];
            G.x += gz[c] * w0; G.y += gz[c] * w1;
            B.x += bz[c] * w0; B.y += bz[c] * w1;
        }
        d_G2[tid] = G; d_B2[tid] = B;
    }
}

// ---------------- 1) LayerNorm over a: [1024][768] -------------------------
__global__ void ln_a_kernel(const float* __restrict__ a, const float* __restrict__ g,
                            const float* __restrict__ b) {
    int row = blockIdx.x, tid = threadIdx.x;
    const float* x = a + (size_t)row * CQ;
    float v0 = x[tid], v1 = x[tid + 256], v2 = x[tid + 512];
    float s = v0 + v1 + v2;
    float s2 = v0 * v0 + v1 * v1 + v2 * v2;
#pragma unroll
    for (int o = 16; o; o >>= 1) {
        s  += __shfl_xor_sync(0xffffffffu, s, o);
        s2 += __shfl_xor_sync(0xffffffffu, s2, o);
    }
    __shared__ float rs[8], rs2[8], bc[2];
    int w = tid >> 5;
    if ((tid & 31) == 0) { rs[w] = s; rs2[w] = s2; }
    __syncthreads();
    if (tid == 0) {
        float S = 0.f, S2 = 0.f;
        for (int i = 0; i < 8; i++) { S += rs[i]; S2 += rs2[i]; }
        float mu = S * (1.f / 768.f);
        float var = S2 * (1.f / 768.f) - mu * mu;
        bc[0] = mu; bc[1] = rsqrtf(var + 1e-5f);
    }
    __syncthreads();
    float mu = bc[0], rstd = bc[1];
    float* o = d_an + (size_t)row * CQ;
    o[tid]       = (v0 - mu) * rstd * g[tid]       + b[tid];
    o[tid + 256] = (v1 - mu) * rstd * g[tid + 256] + b[tid + 256];
    o[tid + 512] = (v2 - mu) * rstd * g[tid + 512] + b[tid + 512];
}

// ---------------- 2) fused q/k/v/g projections (grid.z selects weight) -----
// sel==1 (k) additionally writes transposed copy to d_kT[hd][tok].
__global__ void qkvg_proj_kernel(const float* __restrict__ wq, const float* __restrict__ wk,
                                 const float* __restrict__ wv, const float* __restrict__ wg,
                                 const float* __restrict__ bg) {
    __shared__ float As[16][68];
    __shared__ float Bs[16][64];
    __shared__ float ts[64][68];   // transpose stage (sel==1 only)
    const int K = CQ, N = HDM, ldc = 4 * HDM;
    int sel = blockIdx.z;
    const float* W = (sel == 0) ? wq : (sel == 1) ? wk : (sel == 2) ? wv : wg;
    int tid = threadIdx.x;
    int m_blk = blockIdx.y * 64, n_blk = blockIdx.x * 64;
    int tx = tid & 15, ty = tid >> 4;
    int ar = tid >> 2, ac4 = tid & 3;
    int br = tid >> 4, bc4 = tid & 15;
    const float* Ap = d_an + (size_t)(m_blk + ar) * K + ac4 * 4;
    const float* Wp = W + (size_t)br * N + n_blk + bc4 * 4;
    float2 acc[4][2];
#pragma unroll
    for (int i = 0; i < 4; i++) { acc[i][0] = make_float2(0.f, 0.f); acc[i][1] = make_float2(0.f, 0.f); }
    for (int k0 = 0; k0 < K; k0 += 16) {
        float4 av = *(const float4*)(Ap + k0);
        float4 bv = *(const float4*)(Wp + (size_t)k0 * N);
        __syncthreads();
        As[ac4 * 4 + 0][ar] = av.x; As[ac4 * 4 + 1][ar] = av.y;
        As[ac4 * 4 + 2][ar] = av.z; As[ac4 * 4 + 3][ar] = av.w;
        *(float4*)&Bs[br][bc4 * 4] = bv;
        __syncthreads();
#pragma unroll
        for (int kk = 0; kk < 16; ++kk) {
            float4 a4 = *(const float4*)&As[kk][ty * 4];
            float4 b4 = *(const float4*)&Bs[kk][tx * 4];
            float2 b01 = make_float2(b4.x, b4.y), b23 = make_float2(b4.z, b4.w);
            acc[0][0] = ffma2(f2b(a4.x), b01, acc[0][0]); acc[0][1] = ffma2(f2b(a4.x), b23, acc[0][1]);
            acc[1][0] = ffma2(f2b(a4.y), b01, acc[1][0]); acc[1][1] = ffma2(f2b(a4.y), b23, acc[1][1]);
            acc[2][0] = ffma2(f2b(a4.z), b01, acc[2][0]); acc[2][1] = ffma2(f2b(a4.z), b23, acc[2][1]);
            acc[3][0] = ffma2(f2b(a4.w), b01, acc[3][0]); acc[3][1] = ffma2(f2b(a4.w), b23, acc[3][1]);
        }
    }
    const float qscale = 0.14433756729740643f;  // 1/sqrt(48)
#pragma unroll
    for (int i = 0; i < 4; i++) {
        int m = m_blk + ty * 4 + i;
        float vals[4] = { acc[i][0].x, acc[i][0].y, acc[i][1].x, acc[i][1].y };
        float4 o;
#pragma unroll
        for (int jn = 0; jn < 4; jn++) {
            int n = n_blk + tx * 4 + jn;
            float v = vals[jn];
            if (sel == 0) v *= qscale;
            else if (sel == 3) v = 1.f / (1.f + __expf(-(v + bg[n])));
            ((float*)&o)[jn] = v;
        }
        *(float4*)(d_qkvg + (size_t)m * ldc + sel * 768 + n_blk + tx * 4) = o;
        if (sel == 1) {
            ts[tx * 4 + 0][ty * 4 + i] = vals[0];
            ts[tx * 4 + 1][ty * 4 + i] = vals[1];
            ts[tx * 4 + 2][ty * 4 + i] = vals[2];
            ts[tx * 4 + 3][ty * 4 + i] = vals[3];
        }
    }
    if (sel == 1) {
        __syncthreads();
        for (int idx = tid; idx < 1024; idx += 256) {
            int n = idx >> 4, m4 = idx & 15;
            *(float4*)(d_kT + (size_t)(n_blk + n) * N_TOK + m_blk + m4 * 4) =
                *(const float4*)&ts[n][m4 * 4];
        }
    }
}

// ---------------- 3) pair bias: raw-z GEMM + deferred LN affine ------------
// pb[h,i,j] = rstd_j*(dot(z_j, gw_h) - mu_j*G_h) + B_h + maskbias
__global__ void __launch_bounds__(256) pair_bias_kernel(
        const float* __restrict__ z, const float* __restrict__ mask) {
    __shared__ float zs[64][132];      // RAW z rows (also reused as stage)
    __shared__ float2 wt[8][130];      // g.*w_z head-pair packed, padded stride
    __shared__ float mus[64], rst[64];
    int i = blockIdx.y;
    int j0 = blockIdx.x * 64;
    int tid = threadIdx.x;
    int warp = tid >> 5, lane = tid & 31;

    for (int idx = tid; idx < 1024; idx += 256) {
        int hp = idx >> 7, c = idx & 127;
        wt[hp][c] = d_gwT[hp * 130 + c];
    }

    // stage raw z immediately; reductions run behind the loads
#pragma unroll
    for (int rr = 0; rr < 8; ++rr) {
        int r = warp * 8 + rr;
        const float4 v = *(const float4*)(z + ((size_t)i * N_TOK + (j0 + r)) * CZ + lane * 4);
        *(float4*)&zs[r][lane * 4] = v;
        float s  = v.x + v.y + v.z + v.w;
        float s2 = v.x * v.x + v.y * v.y + v.z * v.z + v.w * v.w;
#pragma unroll
        for (int o = 16; o; o >>= 1) {
            s  += __shfl_xor_sync(0xffffffffu, s, o);
            s2 += __shfl_xor_sync(0xffffffffu, s2, o);
        }
        if (lane == 0) {
            float mu = s * (1.f / 128.f);
            float var = s2 * (1.f / 128.f) - mu * mu;
            mus[r] = mu;
            rst[r] = rsqrtf(var + 1e-5f);
        }
    }
    __syncthreads();

    int jg = tid >> 3, hp = tid & 7;
    int ja = jg * 2, jb = ja + 1;
    float2 accA = make_float2(0.f, 0.f), accB = accA;
#pragma unroll
    for (int c = 0; c < 128; c += 4) {
        float4 w01 = *(const float4*)&wt[hp][c];
        float4 w23 = *(const float4*)&wt[hp][c + 2];
        float4 za = *(const float4*)&zs[ja][c];
        float4 zb = *(const float4*)&zs[jb][c];
        float2 wA = make_float2(w01.x, w01.y), wB = make_float2(w01.z, w01.w);
        float2 wC = make_float2(w23.x, w23.y), wD = make_float2(w23.z, w23.w);
        accA = ffma2(f2b(za.x), wA, accA); accA = ffma2(f2b(za.y), wB, accA);
        accA = ffma2(f2b(za.z), wC, accA); accA = ffma2(f2b(za.w), wD, accA);
        accB = ffma2(f2b(zb.x), wA, accB); accB = ffma2(f2b(zb.y), wB, accB);
        accB = ffma2(f2b(zb.z), wC, accB); accB = ffma2(f2b(zb.w), wD, accB);
    }
    // deferred LN affine
    float2 Gp = d_G2[hp], Bp = d_B2[hp];
    float muA = mus[ja], rA = rst[ja];
    float muB = mus[jb], rB = rst[jb];
    float oAx = rA * (accA.x - muA * Gp.x) + Bp.x;
    float oAy = rA * (accA.y - muA * Gp.y) + Bp.y;
    float oBx = rB * (accB.x - muB * Gp.x) + Bp.x;
    float oBy = rB * (accB.y - muB * Gp.y) + Bp.y;
    __syncthreads();
    float* stage = &zs[0][0];
    stage[(2 * hp) * 66 + ja]     = oAx;
    stage[(2 * hp + 1) * 66 + ja] = oAy;
    stage[(2 * hp) * 66 + jb]     = oBx;
    stage[(2 * hp + 1) * 66 + jb] = oBy;
    __syncthreads();
    int h = tid >> 4, j4 = (tid & 15) * 4;
    float mi = mask[i];
    float4 mj = *(const float4*)(mask + j0 + j4);
    float4 o;
    o.x = stage[h * 66 + j4 + 0] + 1.0e9f * (mi * mj.x - 1.0f);
    o.y = stage[h * 66 + j4 + 1] + 1.0e9f * (mi * mj.y - 1.0f);
    o.z = stage[h * 66 + j4 + 2] + 1.0e9f * (mi * mj.z - 1.0f);
    o.w = stage[h * 66 + j4 + 3] + 1.0e9f * (mi * mj.w - 1.0f);
    *(float4*)(d_pb + (size_t)h * NN + (size_t)i * N_TOK + j0 + j4) = o;
}

// ---------------- 4) split-k flash attention ------------------------------
__global__ void __launch_bounds__(256) flash_kernel() {
    __shared__ float qs[64][48];     // [q][d]
    __shared__ float ks[48][64];     // [d][k] from d_kT, conflict-free
    __shared__ float vs[64][48];     // [k][d]
    __shared__ float ps[64][68];     // probs
    __shared__ float sc[64];         // per-row rescale
    int q0 = blockIdx.x * 64, h = blockIdx.y, split = blockIdx.z;
    int tid = threadIdx.x;
    int qg = tid >> 4, dg = tid & 15;
    int qp = tid >> 3, dg8 = tid & 7, d0 = dg8 * 6;

    for (int idx = tid; idx < 64 * 12; idx += 256) {
        int r = idx / 12, c4 = idx % 12;
        *(float4*)&qs[r][c4 * 4] =
            *(const float4*)(d_qkvg + (size_t)(q0 + r) * 3072 + h * 48 + c4 * 4);
    }

    float2 oA0 = make_float2(0.f, 0.f), oA1 = oA0, oA2 = oA0;
    float2 oB0 = oA0, oB1 = oA0, oB2 = oA0;
    float m[4], l[4];
#pragma unroll
    for (int i = 0; i < 4; i++) { m[i] = -1e30f; l[i] = 0.f; }

    int kbeg = split * (N_TOK / KSPLIT), kend = kbeg + (N_TOK / KSPLIT);
    for (int k0 = kbeg; k0 < kend; k0 += 64) {
        __syncthreads();
        for (int idx = tid; idx < 48 * 16; idx += 256) {
            int d = idx >> 4, c = idx & 15;
            *(float4*)&ks[d][c * 4] =
                *(const float4*)(d_kT + (size_t)(h * 48 + d) * N_TOK + k0 + c * 4);
        }
        for (int idx = tid; idx < 64 * 12; idx += 256) {
            int r = idx / 12, c4 = idx % 12;
            *(float4*)&vs[r][c4 * 4] =
                *(const float4*)(d_qkvg + (size_t)(k0 + r) * 3072 + 1536 + h * 48 + c4 * 4);
        }
        float2 s[4][2];
#pragma unroll
        for (int i = 0; i < 4; i++) {
            float4 p = *(const float4*)(d_pb + (size_t)h * NN +
                                        (size_t)(q0 + qg + 16 * i) * N_TOK + k0 + dg * 4);
            s[i][0] = make_float2(p.x, p.y); s[i][1] = make_float2(p.z, p.w);
        }
        __syncthreads();

#pragma unroll 8
        for (int d = 0; d < 48; ++d) {
            float4 kv = *(const float4*)&ks[d][dg * 4];
            float2 k01 = make_float2(kv.x, kv.y), k23 = make_float2(kv.z, kv.w);
#pragma unroll
            for (int i = 0; i < 4; i++) {
                float2 q = f2b(qs[qg + 16 * i][d]);
                s[i][0] = ffma2(q, k01, s[i][0]);
                s[i][1] = ffma2(q, k23, s[i][1]);
            }
        }
#pragma unroll
        for (int i = 0; i < 4; i++) {
            float tm = fmaxf(fmaxf(s[i][0].x, s[i][0].y), fmaxf(s[i][1].x, s[i][1].y));
#pragma unroll
            for (int o = 1; o < 16; o <<= 1) tm = fmaxf(tm, __shfl_xor_sync(0xffffffffu, tm, o));
            float mn = fmaxf(m[i], tm);
            float scl = __expf(m[i] - mn);
            float2 e0, e1;
            e0.x = __expf(s[i][0].x - mn); e0.y = __expf(s[i][0].y - mn);
            e1.x = __expf(s[i][1].x - mn); e1.y = __expf(s[i][1].y - mn);
            float sum = e0.x + e0.y + e1.x + e1.y;
#pragma unroll
            for (int o = 1; o < 16; o <<= 1) sum += __shfl_xor_sync(0xffffffffu, sum, o);
            l[i] = l[i] * scl + sum;
            m[i] = mn;
            *(float2*)&ps[qg + 16 * i][dg * 4] = e0;
            *(float2*)&ps[qg + 16 * i][dg * 4 + 2] = e1;
            if (dg == 0) sc[qg + 16 * i] = scl;
        }
        __syncthreads();

        float sA = sc[qp], sB = sc[qp + 32];
        oA0.x *= sA; oA0.y *= sA; oA1.x *= sA; oA1.y *= sA; oA2.x *= sA; oA2.y *= sA;
        oB0.x *= sB; oB0.y *= sB; oB1.x *= sB; oB1.y *= sB; oB2.x *= sB; oB2.y *= sB;
#pragma unroll 16
        for (int kk = 0; kk < 64; ++kk) {
            float2 v01 = *(const float2*)&vs[kk][d0];
            float2 v23 = *(const float2*)&vs[kk][d0 + 2];
            float2 v45 = *(const float2*)&vs[kk][d0 + 4];
            float2 pa = f2b(ps[qp][kk]);
            float2 pb2 = f2b(ps[qp + 32][kk]);
            oA0 = ffma2(pa, v01, oA0); oA1 = ffma2(pa, v23, oA1); oA2 = ffma2(pa, v45, oA2);
            oB0 = ffma2(pb2, v01, oB0); oB1 = ffma2(pb2, v23, oB1); oB2 = ffma2(pb2, v45, oB2);
        }
    }
    size_t obase = ((size_t)split * NH + h) * N_TOK;
    float* opA = d_ospl + (obase + q0 + qp) * HD + d0;
    float* opB = d_ospl + (obase + q0 + qp + 32) * HD + d0;
    opA[0] = oA0.x; opA[1] = oA0.y; opA[2] = oA1.x;
    opA[3] = oA1.y; opA[4] = oA2.x; opA[5] = oA2.y;
    opB[0] = oB0.x; opB[1] = oB0.y; opB[2] = oB1.x;
    opB[3] = oB1.y; opB[4] = oB2.x; opB[5] = oB2.y;
    if (dg == 0) {
#pragma unroll
        for (int i = 0; i < 4; i++) {
            d_ml[(obase + q0 + qg + 16 * i) * 2]     = m[i];
            d_ml[(obase + q0 + qg + 16 * i) * 2 + 1] = l[i];
        }
    }
}

// ---------------- 4b) combine splits + gate --------------------------------
__global__ void combine_kernel() {
    int idx = blockIdx.x * 256 + threadIdx.x;        // 16*1024*48
    int d = idx % HD;
    int hq = idx / HD;
    int q = hq & (N_TOK - 1);
    int h = hq >> 10;
    size_t row = (size_t)h * N_TOK + q;
    float m[KSPLIT], l[KSPLIT];
    float mx = -1e30f;
#pragma unroll
    for (int s = 0; s < KSPLIT; ++s) {
        m[s] = d_ml[((size_t)s * NH * N_TOK + row) * 2];
        l[s] = d_ml[((size_t)s * NH * N_TOK + row) * 2 + 1];
        mx = fmaxf(mx, m[s]);
    }
    float lt = 0.f, ov = 0.f;
#pragma unroll
    for (int s = 0; s < KSPLIT; ++s) {
        float w = __expf(m[s] - mx);
        lt += l[s] * w;
        ov += d_ospl[((size_t)s * NH * N_TOK + row) * HD + d] * w;
    }
    float g = d_qkvg[(size_t)q * 3072 + 2304 + h * 48 + d];
    d_og[(size_t)q * HDM + h * 48 + d] = ov / lt * g;
}

// ---------------- 5) output projection: og @ w_o + b_o (32x64 tiles) -------
__global__ void out_proj_kernel(const float* __restrict__ W, const float* __restrict__ bias,
                                float* __restrict__ C) {
    __shared__ float As[16][36];
    __shared__ float Bs[16][64];
    const int K = HDM, N = CQ, ldc = CQ;
    int tid = threadIdx.x;
    int m_blk = blockIdx.y * 32, n_blk = blockIdx.x * 64;
    int tx = tid & 15, ty = tid >> 4;
    int ar = tid >> 3, ac2 = tid & 7;
    int br = tid >> 4, bc4 = tid & 15;
    const float* Ap = d_og + (size_t)(m_blk + ar) * K + ac2 * 2;
    const float* Wp = W + (size_t)br * N + n_blk + bc4 * 4;
    float2 acc[2][2];
#pragma unroll
    for (int i = 0; i < 2; i++) { acc[i][0] = make_float2(0.f, 0.f); acc[i][1] = make_float2(0.f, 0.f); }
    for (int k0 = 0; k0 < K; k0 += 16) {
        float2 av = *(const float2*)(Ap + k0);
        float4 bv = *(const float4*)(Wp + (size_t)k0 * N);
        __syncthreads();
        As[ac2 * 2 + 0][ar] = av.x;
        As[ac2 * 2 + 1][ar] = av.y;
        *(float4*)&Bs[br][bc4 * 4] = bv;
        __syncthreads();
#pragma unroll
        for (int kk = 0; kk < 16; ++kk) {
            float2 a2 = *(const float2*)&As[kk][ty * 2];
            float4 b4 = *(const float4*)&Bs[kk][tx * 4];
            float2 b01 = make_float2(b4.x, b4.y), b23 = make_float2(b4.z, b4.w);
            acc[0][0] = ffma2(f2b(a2.x), b01, acc[0][0]); acc[0][1] = ffma2(f2b(a2.x), b23, acc[0][1]);
            acc[1][0] = ffma2(f2b(a2.y), b01, acc[1][0]); acc[1][1] = ffma2(f2b(a2.y), b23, acc[1][1]);
        }
    }
#pragma unroll
    for (int i = 0; i < 2; i++) {
        int m = m_blk + ty * 2 + i;
        float vals[4] = { acc[i][0].x, acc[i][0].y, acc[i][1].x, acc[i][1].y };
        float4 o;
#pragma unroll
        for (int jn = 0; jn < 4; jn++) {
            int n = n_blk + tx * 4 + jn;
            ((float*)&o)[jn] = vals[jn] + bias[n];
        }
        *(float4*)(C + (size_t)m * ldc + n_blk + tx * 4) = o;
    }
}

// ---------------- launch ---------------------------------------------------
extern "C" void kernel_launch(void* const* d_in, const int* in_sizes, int n_in,
                              void* d_out, int out_size) {
    const float* a    = (const float*)d_in[0];
    const float* z    = (const float*)d_in[1];
    const float* mask = (const float*)d_in[2];
    const float* g_a  = (const float*)d_in[3];
    const float* b_a  = (const float*)d_in[4];
    const float* g_z  = (const float*)d_in[5];
    const float* b_z  = (const float*)d_in[6];
    const float* w_z  = (const float*)d_in[7];
    const float* w_q  = (const float*)d_in[8];
    const float* w_k  = (const float*)d_in[9];
    const float* w_v  = (const float*)d_in[10];
    const float* w_g  = (const float*)d_in[11];
    const float* b_g  = (const float*)d_in[12];
    const float* w_o  = (const float*)d_in[13];
    const float* b_o  = (const float*)d_in[14];
    float* out = (float*)d_out;

    static cudaStream_t s2 = nullptr;
    static cudaEvent_t evF = nullptr, evJ = nullptr;
    if (s2 == nullptr) {
        cudaStreamCreateWithFlags(&s2, cudaStreamNonBlocking);
        cudaEventCreateWithFlags(&evF, cudaEventDisableTiming);
        cudaEventCreateWithFlags(&evJ, cudaEventDisableTiming);
    }

    // main stream: setup -> fork pair_bias onto s2; ln+qkvg run concurrently
    setup_kernel<<<1, 256>>>(g_z, b_z, w_z);
    cudaEventRecord(evF, 0);
    cudaStreamWaitEvent(s2, evF, 0);
    pair_bias_kernel<<<dim3(N_TOK / 64, N_TOK), 256, 0, s2>>>(z, mask);
    cudaEventRecord(evJ, s2);

    ln_a_kernel<<<N_TOK, 256>>>(a, g_a, b_a);
    qkvg_proj_kernel<<<dim3(HDM / 64, N_TOK / 64, 4), 256>>>(w_q, w_k, w_v, w_g, b_g);

    cudaStreamWaitEvent(0, evJ, 0);   // join: flash needs pb + qkvg
    flash_kernel<<<dim3(N_TOK / 64, NH, KSPLIT), 256>>>();
    combine_kernel<<<(NH * N_TOK * HD) / 256, 256>>>();

    out_proj_kernel<<<dim3(CQ / 64, N_TOK / 32), 256>>>(w_o, b_o, out);
}

// round 12
// speedup vs baseline: 2.3344x; 1.0811x over previous
#include <cuda_runtime.h>
#include <math.h>

#define N_TOK 1024
#define CQ    768
#define CZ    128
#define NH    16
#define HD    48
#define HDM   (NH*HD)              // 768
#define NN    ((size_t)N_TOK*(size_t)N_TOK)
#define KSPLIT 4

// ---------------- scratch (device globals: no allocation allowed) ----------
__device__ float d_an[N_TOK*CQ];                    // LayerNorm(a)
__device__ float d_qkvg[(size_t)N_TOK*4*HDM];       // [tok][q|k|v|g]
__device__ float d_kT[(size_t)HDM*N_TOK];           // k transposed [hd][tok]
__device__ float d_pb[16ULL*1024ULL*1024ULL];       // pair bias (+mask bias)
__device__ float d_og[N_TOK*HDM];                   // gated attention output
__device__ float d_ospl[(size_t)KSPLIT*NH*N_TOK*HD];// split-k partial o (unnormalized)
__device__ float d_ml[(size_t)KSPLIT*NH*N_TOK*2];   // split-k partial (m, l)
__device__ float2 d_gwT[8*130];                     // (g*w_z) head-pair packed, padded
__device__ float2 d_G2[8];                          // G_h = sum_c g_c w_ch (pairs)
__device__ float2 d_B2[8];                          // B_h = sum_c b_c w_ch (pairs)

// ---------------- f32x2 packed FMA (Blackwell FFMA2, PTX-only) -------------
__device__ __forceinline__ float2 ffma2(float2 a, float2 b, float2 c) {
    float2 d;
    asm("fma.rn.f32x2 %0, %1, %2, %3;"
        : "=l"(reinterpret_cast<unsigned long long&>(d))
        : "l"(reinterpret_cast<unsigned long long&>(a)),
          "l"(reinterpret_cast<unsigned long long&>(b)),
          "l"(reinterpret_cast<unsigned long long&>(c)));
    return d;
}
__device__ __forceinline__ float2 f2b(float x) { return make_float2(x, x); }

// ---------------- 0) setup: gw = g.*w_z (transposed+packed), G, B ----------
__global__ void setup_kernel(const float* __restrict__ gz, const float* __restrict__ bz,
                             const float* __restrict__ wz) {
    int tid = threadIdx.x;  // 256
    for (int idx = tid; idx < 1024; idx += 256) {
        int hp = idx >> 7, c = idx & 127;
        float g = gz[c];
        d_gwT[hp * 130 + c] = make_float2(g * wz[c * 16 + 2 * hp],
                                          g * wz[c * 16 + 2 * hp + 1]);
    }
    if (tid < 8) {
        float2 G = make_float2(0.f, 0.f), B = make_float2(0.f, 0.f);
        for (int c = 0; c < 128; ++c) {
            float w0 = wz[c * 16 + 2 * tid], w1 = wz[c * 16 + 2 * tid + 1];
            G.x += gz[c] * w0; G.y += gz[c] * w1;
            B.x += bz[c] * w0; B.y += bz[c] * w1;
        }
        d_G2[tid] = G; d_B2[tid] = B;
    }
}

// ---------------- 1) LayerNorm over a: [1024][768] -------------------------
__global__ void ln_a_kernel(const float* __restrict__ a, const float* __restrict__ g,
                            const float* __restrict__ b) {
    int row = blockIdx.x, tid = threadIdx.x;
    const float* x = a + (size_t)row * CQ;
    float v0 = x[tid], v1 = x[tid + 256], v2 = x[tid + 512];
    float s = v0 + v1 + v2;
    float s2 = v0 * v0 + v1 * v1 + v2 * v2;
#pragma unroll
    for (int o = 16; o; o >>= 1) {
        s  += __shfl_xor_sync(0xffffffffu, s, o);
        s2 += __shfl_xor_sync(0xffffffffu, s2, o);
    }
    __shared__ float rs[8], rs2[8], bc[2];
    int w = tid >> 5;
    if ((tid & 31) == 0) { rs[w] = s; rs2[w] = s2; }
    __syncthreads();
    if (tid == 0) {
        float S = 0.f, S2 = 0.f;
        for (int i = 0; i < 8; i++) { S += rs[i]; S2 += rs2[i]; }
        float mu = S * (1.f / 768.f);
        float var = S2 * (1.f / 768.f) - mu * mu;
        bc[0] = mu; bc[1] = rsqrtf(var + 1e-5f);
    }
    __syncthreads();
    float mu = bc[0], rstd = bc[1];
    float* o = d_an + (size_t)row * CQ;
    o[tid]       = (v0 - mu) * rstd * g[tid]       + b[tid];
    o[tid + 256] = (v1 - mu) * rstd * g[tid + 256] + b[tid + 256];
    o[tid + 512] = (v2 - mu) * rstd * g[tid + 512] + b[tid + 512];
}

// ---------------- 2) fused q/k/v/g projections (grid.z selects weight) -----
// sel==1 (k) additionally writes transposed copy to d_kT[hd][tok].
__global__ void qkvg_proj_kernel(const float* __restrict__ wq, const float* __restrict__ wk,
                                 const float* __restrict__ wv, const float* __restrict__ wg,
                                 const float* __restrict__ bg) {
    __shared__ float As[16][68];
    __shared__ float Bs[16][64];
    __shared__ float ts[64][68];   // transpose stage (sel==1 only)
    const int K = CQ, N = HDM, ldc = 4 * HDM;
    int sel = blockIdx.z;
    const float* W = (sel == 0) ? wq : (sel == 1) ? wk : (sel == 2) ? wv : wg;
    int tid = threadIdx.x;
    int m_blk = blockIdx.y * 64, n_blk = blockIdx.x * 64;
    int tx = tid & 15, ty = tid >> 4;
    int ar = tid >> 2, ac4 = tid & 3;
    int br = tid >> 4, bc4 = tid & 15;
    const float* Ap = d_an + (size_t)(m_blk + ar) * K + ac4 * 4;
    const float* Wp = W + (size_t)br * N + n_blk + bc4 * 4;
    float2 acc[4][2];
#pragma unroll
    for (int i = 0; i < 4; i++) { acc[i][0] = make_float2(0.f, 0.f); acc[i][1] = make_float2(0.f, 0.f); }
    for (int k0 = 0; k0 < K; k0 += 16) {
        float4 av = *(const float4*)(Ap + k0);
        float4 bv = *(const float4*)(Wp + (size_t)k0 * N);
        __syncthreads();
        As[ac4 * 4 + 0][ar] = av.x; As[ac4 * 4 + 1][ar] = av.y;
        As[ac4 * 4 + 2][ar] = av.z; As[ac4 * 4 + 3][ar] = av.w;
        *(float4*)&Bs[br][bc4 * 4] = bv;
        __syncthreads();
#pragma unroll
        for (int kk = 0; kk < 16; ++kk) {
            float4 a4 = *(const float4*)&As[kk][ty * 4];
            float4 b4 = *(const float4*)&Bs[kk][tx * 4];
            float2 b01 = make_float2(b4.x, b4.y), b23 = make_float2(b4.z, b4.w);
            acc[0][0] = ffma2(f2b(a4.x), b01, acc[0][0]); acc[0][1] = ffma2(f2b(a4.x), b23, acc[0][1]);
            acc[1][0] = ffma2(f2b(a4.y), b01, acc[1][0]); acc[1][1] = ffma2(f2b(a4.y), b23, acc[1][1]);
            acc[2][0] = ffma2(f2b(a4.z), b01, acc[2][0]); acc[2][1] = ffma2(f2b(a4.z), b23, acc[2][1]);
            acc[3][0] = ffma2(f2b(a4.w), b01, acc[3][0]); acc[3][1] = ffma2(f2b(a4.w), b23, acc[3][1]);
        }
    }
    const float qscale = 0.14433756729740643f;  // 1/sqrt(48)
#pragma unroll
    for (int i = 0; i < 4; i++) {
        int m = m_blk + ty * 4 + i;
        float vals[4] = { acc[i][0].x, acc[i][0].y, acc[i][1].x, acc[i][1].y };
        float4 o;
#pragma unroll
        for (int jn = 0; jn < 4; jn++) {
            int n = n_blk + tx * 4 + jn;
            float v = vals[jn];
            if (sel == 0) v *= qscale;
            else if (sel == 3) v = 1.f / (1.f + __expf(-(v + bg[n])));
            ((float*)&o)[jn] = v;
        }
        *(float4*)(d_qkvg + (size_t)m * ldc + sel * 768 + n_blk + tx * 4) = o;
        if (sel == 1) {
            ts[tx * 4 + 0][ty * 4 + i] = vals[0];
            ts[tx * 4 + 1][ty * 4 + i] = vals[1];
            ts[tx * 4 + 2][ty * 4 + i] = vals[2];
            ts[tx * 4 + 3][ty * 4 + i] = vals[3];
        }
    }
    if (sel == 1) {
        __syncthreads();
        for (int idx = tid; idx < 1024; idx += 256) {
            int n = idx >> 4, m4 = idx & 15;
            *(float4*)(d_kT + (size_t)(n_blk + n) * N_TOK + m_blk + m4 * 4) =
                *(const float4*)&ts[n][m4 * 4];
        }
    }
}

// ---------------- 3) pair bias v3: raw-z GEMM, 4j x 2hp x cS4 micro --------
// pb[h,i,j] = rstd_j*(dot(z_j, gw_h) - mu_j*G_h) + B_h + maskbias
__global__ void __launch_bounds__(256) pair_bias_kernel(
        const float* __restrict__ z, const float* __restrict__ mask) {
    __shared__ float zs[64][132];      // raw z rows; later aliased as partial stage
    __shared__ float2 wt[8][130];      // g.*w_z head-pair packed; later stage2
    __shared__ float mus[64], rst[64];
    float* st     = &zs[0][0];         // [4][64][20] = 5120 floats (< 8448)
    float* stage2 = (float*)&wt[0][0]; // [16][66]   = 1056 floats (< 2080)

    int i = blockIdx.y;
    int j0 = blockIdx.x * 64;
    int tid = threadIdx.x;
    int warp = tid >> 5, lane = tid & 31;

    for (int idx = tid; idx < 1024; idx += 256) {
        int hp = idx >> 7, c = idx & 127;
        wt[hp][c] = d_gwT[hp * 130 + c];
    }

    // Phase A: stage raw z + row stats
#pragma unroll
    for (int rr = 0; rr < 8; ++rr) {
        int r = warp * 8 + rr;
        const float4 v = *(const float4*)(z + ((size_t)i * N_TOK + (j0 + r)) * CZ + lane * 4);
        *(float4*)&zs[r][lane * 4] = v;
        float s  = v.x + v.y + v.z + v.w;
        float s2 = v.x * v.x + v.y * v.y + v.z * v.z + v.w * v.w;
#pragma unroll
        for (int o = 16; o; o >>= 1) {
            s  += __shfl_xor_sync(0xffffffffu, s, o);
            s2 += __shfl_xor_sync(0xffffffffu, s2, o);
        }
        if (lane == 0) {
            float mu = s * (1.f / 128.f);
            float var = s2 * (1.f / 128.f) - mu * mu;
            mus[r] = mu;
            rst[r] = rsqrtf(var + 1e-5f);
        }
    }
    __syncthreads();

    // Phase B: GEMM. thread = (cS, jG, hpG): rows jG+16r (r=0..3), heads 4hpG..4hpG+3
    int cS = tid >> 6;          // 0..3, 32 c each
    int t  = tid & 63;
    int jG = t >> 2;            // 0..15
    int hpG = t & 3;            // hp0 = 2hpG, hp1 = 2hpG+1
    float2 acc[4][2];
#pragma unroll
    for (int r = 0; r < 4; ++r) { acc[r][0] = make_float2(0.f, 0.f); acc[r][1] = make_float2(0.f, 0.f); }
    int c0 = cS * 32;
#pragma unroll
    for (int cc = 0; cc < 32; cc += 4) {
        int c = c0 + cc;
        float4 w00 = *(const float4*)&wt[2 * hpG][c];        // hp0: cols c, c+1
        float4 w01 = *(const float4*)&wt[2 * hpG][c + 2];    // hp0: cols c+2, c+3
        float4 w10 = *(const float4*)&wt[2 * hpG + 1][c];    // hp1
        float4 w11 = *(const float4*)&wt[2 * hpG + 1][c + 2];
        float2 wA0 = make_float2(w00.x, w00.y), wA1 = make_float2(w00.z, w00.w);
        float2 wA2 = make_float2(w01.x, w01.y), wA3 = make_float2(w01.z, w01.w);
        float2 wB0 = make_float2(w10.x, w10.y), wB1 = make_float2(w10.z, w10.w);
        float2 wB2 = make_float2(w11.x, w11.y), wB3 = make_float2(w11.z, w11.w);
#pragma unroll
        for (int r = 0; r < 4; ++r) {
            float4 zq = *(const float4*)&zs[jG + 16 * r][c];
            acc[r][0] = ffma2(f2b(zq.x), wA0, acc[r][0]);
            acc[r][0] = ffma2(f2b(zq.y), wA1, acc[r][0]);
            acc[r][0] = ffma2(f2b(zq.z), wA2, acc[r][0]);
            acc[r][0] = ffma2(f2b(zq.w), wA3, acc[r][0]);
            acc[r][1] = ffma2(f2b(zq.x), wB0, acc[r][1]);
            acc[r][1] = ffma2(f2b(zq.y), wB1, acc[r][1]);
            acc[r][1] = ffma2(f2b(zq.z), wB2, acc[r][1]);
            acc[r][1] = ffma2(f2b(zq.w), wB3, acc[r][1]);
        }
    }
    __syncthreads();   // zs reads done; reuse as partial stage st[cS][j][20]

#pragma unroll
    for (int r = 0; r < 4; ++r) {
        int j = jG + 16 * r;
        float4 v = make_float4(acc[r][0].x, acc[r][0].y, acc[r][1].x, acc[r][1].y);
        *(float4*)&st[(cS * 64 + j) * 20 + 4 * hpG] = v;
    }
    __syncthreads();

    // Phase C: reduce over cS + deferred LN affine -> stage2[h][j]
    {
        int j = tid >> 2, hg = tid & 3;   // heads hg*4..hg*4+3
        float4 s0 = *(const float4*)&st[(0 * 64 + j) * 20 + hg * 4];
        float4 s1 = *(const float4*)&st[(1 * 64 + j) * 20 + hg * 4];
        float4 s2v = *(const float4*)&st[(2 * 64 + j) * 20 + hg * 4];
        float4 s3 = *(const float4*)&st[(3 * 64 + j) * 20 + hg * 4];
        float4 sum = make_float4(s0.x + s1.x + s2v.x + s3.x,
                                 s0.y + s1.y + s2v.y + s3.y,
                                 s0.z + s1.z + s2v.z + s3.z,
                                 s0.w + s1.w + s2v.w + s3.w);
        float mu = mus[j], rd = rst[j];
        float2 G0 = d_G2[2 * hg], G1 = d_G2[2 * hg + 1];
        float2 B0 = d_B2[2 * hg], B1 = d_B2[2 * hg + 1];
        float o0 = rd * (sum.x - mu * G0.x) + B0.x;
        float o1 = rd * (sum.y - mu * G0.y) + B0.y;
        float o2 = rd * (sum.z - mu * G1.x) + B1.x;
        float o3 = rd * (sum.w - mu * G1.y) + B1.y;
        stage2[(4 * hg + 0) * 66 + j] = o0;
        stage2[(4 * hg + 1) * 66 + j] = o1;
        stage2[(4 * hg + 2) * 66 + j] = o2;
        stage2[(4 * hg + 3) * 66 + j] = o3;
    }
    __syncthreads();

    // Phase D: coalesced store + mask bias
    {
        int h = tid >> 4, j4 = (tid & 15) * 4;
        float mi = mask[i];
        float4 mj = *(const float4*)(mask + j0 + j4);
        float4 o;
        o.x = stage2[h * 66 + j4 + 0] + 1.0e9f * (mi * mj.x - 1.0f);
        o.y = stage2[h * 66 + j4 + 1] + 1.0e9f * (mi * mj.y - 1.0f);
        o.z = stage2[h * 66 + j4 + 2] + 1.0e9f * (mi * mj.z - 1.0f);
        o.w = stage2[h * 66 + j4 + 3] + 1.0e9f * (mi * mj.w - 1.0f);
        *(float4*)(d_pb + (size_t)h * NN + (size_t)i * N_TOK + j0 + j4) = o;
    }
}

// ---------------- 4) split-k flash attention ------------------------------
__global__ void __launch_bounds__(256) flash_kernel() {
    __shared__ float qs[64][48];     // [q][d]
    __shared__ float ks[48][64];     // [d][k] from d_kT, conflict-free
    __shared__ float vs[64][48];     // [k][d]
    __shared__ float ps[64][68];     // probs
    __shared__ float sc[64];         // per-row rescale
    int q0 = blockIdx.x * 64, h = blockIdx.y, split = blockIdx.z;
    int tid = threadIdx.x;
    int qg = tid >> 4, dg = tid & 15;
    int qp = tid >> 3, dg8 = tid & 7, d0 = dg8 * 6;

    for (int idx = tid; idx < 64 * 12; idx += 256) {
        int r = idx / 12, c4 = idx % 12;
        *(float4*)&qs[r][c4 * 4] =
            *(const float4*)(d_qkvg + (size_t)(q0 + r) * 3072 + h * 48 + c4 * 4);
    }

    float2 oA0 = make_float2(0.f, 0.f), oA1 = oA0, oA2 = oA0;
    float2 oB0 = oA0, oB1 = oA0, oB2 = oA0;
    float m[4], l[4];
#pragma unroll
    for (int i = 0; i < 4; i++) { m[i] = -1e30f; l[i] = 0.f; }

    int kbeg = split * (N_TOK / KSPLIT), kend = kbeg + (N_TOK / KSPLIT);
    for (int k0 = kbeg; k0 < kend; k0 += 64) {
        __syncthreads();
        for (int idx = tid; idx < 48 * 16; idx += 256) {
            int d = idx >> 4, c = idx & 15;
            *(float4*)&ks[d][c * 4] =
                *(const float4*)(d_kT + (size_t)(h * 48 + d) * N_TOK + k0 + c * 4);
        }
        for (int idx = tid; idx < 64 * 12; idx += 256) {
            int r = idx / 12, c4 = idx % 12;
            *(float4*)&vs[r][c4 * 4] =
                *(const float4*)(d_qkvg + (size_t)(k0 + r) * 3072 + 1536 + h * 48 + c4 * 4);
        }
        float2 s[4][2];
#pragma unroll
        for (int i = 0; i < 4; i++) {
            float4 p = *(const float4*)(d_pb + (size_t)h * NN +
                                        (size_t)(q0 + qg + 16 * i) * N_TOK + k0 + dg * 4);
            s[i][0] = make_float2(p.x, p.y); s[i][1] = make_float2(p.z, p.w);
        }
        __syncthreads();

#pragma unroll 8
        for (int d = 0; d < 48; ++d) {
            float4 kv = *(const float4*)&ks[d][dg * 4];
            float2 k01 = make_float2(kv.x, kv.y), k23 = make_float2(kv.z, kv.w);
#pragma unroll
            for (int i = 0; i < 4; i++) {
                float2 q = f2b(qs[qg + 16 * i][d]);
                s[i][0] = ffma2(q, k01, s[i][0]);
                s[i][1] = ffma2(q, k23, s[i][1]);
            }
        }
#pragma unroll
        for (int i = 0; i < 4; i++) {
            float tm = fmaxf(fmaxf(s[i][0].x, s[i][0].y), fmaxf(s[i][1].x, s[i][1].y));
#pragma unroll
            for (int o = 1; o < 16; o <<= 1) tm = fmaxf(tm, __shfl_xor_sync(0xffffffffu, tm, o));
            float mn = fmaxf(m[i], tm);
            float scl = __expf(m[i] - mn);
            float2 e0, e1;
            e0.x = __expf(s[i][0].x - mn); e0.y = __expf(s[i][0].y - mn);
            e1.x = __expf(s[i][1].x - mn); e1.y = __expf(s[i][1].y - mn);
            float sum = e0.x + e0.y + e1.x + e1.y;
#pragma unroll
            for (int o = 1; o < 16; o <<= 1) sum += __shfl_xor_sync(0xffffffffu, sum, o);
            l[i] = l[i] * scl + sum;
            m[i] = mn;
            *(float2*)&ps[qg + 16 * i][dg * 4] = e0;
            *(float2*)&ps[qg + 16 * i][dg * 4 + 2] = e1;
            if (dg == 0) sc[qg + 16 * i] = scl;
        }
        __syncthreads();

        float sA = sc[qp], sB = sc[qp + 32];
        oA0.x *= sA; oA0.y *= sA; oA1.x *= sA; oA1.y *= sA; oA2.x *= sA; oA2.y *= sA;
        oB0.x *= sB; oB0.y *= sB; oB1.x *= sB; oB1.y *= sB; oB2.x *= sB; oB2.y *= sB;
#pragma unroll 16
        for (int kk = 0; kk < 64; ++kk) {
            float2 v01 = *(const float2*)&vs[kk][d0];
            float2 v23 = *(const float2*)&vs[kk][d0 + 2];
            float2 v45 = *(const float2*)&vs[kk][d0 + 4];
            float2 pa = f2b(ps[qp][kk]);
            float2 pb2 = f2b(ps[qp + 32][kk]);
            oA0 = ffma2(pa, v01, oA0); oA1 = ffma2(pa, v23, oA1); oA2 = ffma2(pa, v45, oA2);
            oB0 = ffma2(pb2, v01, oB0); oB1 = ffma2(pb2, v23, oB1); oB2 = ffma2(pb2, v45, oB2);
        }
    }
    size_t obase = ((size_t)split * NH + h) * N_TOK;
    float* opA = d_ospl + (obase + q0 + qp) * HD + d0;
    float* opB = d_ospl + (obase + q0 + qp + 32) * HD + d0;
    opA[0] = oA0.x; opA[1] = oA0.y; opA[2] = oA1.x;
    opA[3] = oA1.y; opA[4] = oA2.x; opA[5] = oA2.y;
    opB[0] = oB0.x; opB[1] = oB0.y; opB[2] = oB1.x;
    opB[3] = oB1.y; opB[4] = oB2.x; opB[5] = oB2.y;
    if (dg == 0) {
#pragma unroll
        for (int i = 0; i < 4; i++) {
            d_ml[(obase + q0 + qg + 16 * i) * 2]     = m[i];
            d_ml[(obase + q0 + qg + 16 * i) * 2 + 1] = l[i];
        }
    }
}

// ---------------- 4b) combine splits + gate --------------------------------
__global__ void combine_kernel() {
    int idx = blockIdx.x * 256 + threadIdx.x;        // 16*1024*48
    int d = idx % HD;
    int hq = idx / HD;
    int q = hq & (N_TOK - 1);
    int h = hq >> 10;
    size_t row = (size_t)h * N_TOK + q;
    float m[KSPLIT], l[KSPLIT];
    float mx = -1e30f;
#pragma unroll
    for (int s = 0; s < KSPLIT; ++s) {
        m[s] = d_ml[((size_t)s * NH * N_TOK + row) * 2];
        l[s] = d_ml[((size_t)s * NH * N_TOK + row) * 2 + 1];
        mx = fmaxf(mx, m[s]);
    }
    float lt = 0.f, ov = 0.f;
#pragma unroll
    for (int s = 0; s < KSPLIT; ++s) {
        float w = __expf(m[s] - mx);
        lt += l[s] * w;
        ov += d_ospl[((size_t)s * NH * N_TOK + row) * HD + d] * w;
    }
    float g = d_qkvg[(size_t)q * 3072 + 2304 + h * 48 + d];
    d_og[(size_t)q * HDM + h * 48 + d] = ov / lt * g;
}

// ---------------- 5) output projection: og @ w_o + b_o (32x64 tiles) -------
__global__ void out_proj_kernel(const float* __restrict__ W, const float* __restrict__ bias,
                                float* __restrict__ C) {
    __shared__ float As[16][36];
    __shared__ float Bs[16][64];
    const int K = HDM, N = CQ, ldc = CQ;
    int tid = threadIdx.x;
    int m_blk = blockIdx.y * 32, n_blk = blockIdx.x * 64;
    int tx = tid & 15, ty = tid >> 4;
    int ar = tid >> 3, ac2 = tid & 7;
    int br = tid >> 4, bc4 = tid & 15;
    const float* Ap = d_og + (size_t)(m_blk + ar) * K + ac2 * 2;
    const float* Wp = W + (size_t)br * N + n_blk + bc4 * 4;
    float2 acc[2][2];
#pragma unroll
    for (int i = 0; i < 2; i++) { acc[i][0] = make_float2(0.f, 0.f); acc[i][1] = make_float2(0.f, 0.f); }
    for (int k0 = 0; k0 < K; k0 += 16) {
        float2 av = *(const float2*)(Ap + k0);
        float4 bv = *(const float4*)(Wp + (size_t)k0 * N);
        __syncthreads();
        As[ac2 * 2 + 0][ar] = av.x;
        As[ac2 * 2 + 1][ar] = av.y;
        *(float4*)&Bs[br][bc4 * 4] = bv;
        __syncthreads();
#pragma unroll
        for (int kk = 0; kk < 16; ++kk) {
            float2 a2 = *(const float2*)&As[kk][ty * 2];
            float4 b4 = *(const float4*)&Bs[kk][tx * 4];
            float2 b01 = make_float2(b4.x, b4.y), b23 = make_float2(b4.z, b4.w);
            acc[0][0] = ffma2(f2b(a2.x), b01, acc[0][0]); acc[0][1] = ffma2(f2b(a2.x), b23, acc[0][1]);
            acc[1][0] = ffma2(f2b(a2.y), b01, acc[1][0]); acc[1][1] = ffma2(f2b(a2.y), b23, acc[1][1]);
        }
    }
#pragma unroll
    for (int i = 0; i < 2; i++) {
        int m = m_blk + ty * 2 + i;
        float vals[4] = { acc[i][0].x, acc[i][0].y, acc[i][1].x, acc[i][1].y };
        float4 o;
#pragma unroll
        for (int jn = 0; jn < 4; jn++) {
            int n = n_blk + tx * 4 + jn;
            ((float*)&o)[jn] = vals[jn] + bias[n];
        }
        *(float4*)(C + (size_t)m * ldc + n_blk + tx * 4) = o;
    }
}

// ---------------- launch ---------------------------------------------------
extern "C" void kernel_launch(void* const* d_in, const int* in_sizes, int n_in,
                              void* d_out, int out_size) {
    const float* a    = (const float*)d_in[0];
    const float* z    = (const float*)d_in[1];
    const float* mask = (const float*)d_in[2];
    const float* g_a  = (const float*)d_in[3];
    const float* b_a  = (const float*)d_in[4];
    const float* g_z  = (const float*)d_in[5];
    const float* b_z  = (const float*)d_in[6];
    const float* w_z  = (const float*)d_in[7];
    const float* w_q  = (const float*)d_in[8];
    const float* w_k  = (const float*)d_in[9];
    const float* w_v  = (const float*)d_in[10];
    const float* w_g  = (const float*)d_in[11];
    const float* b_g  = (const float*)d_in[12];
    const float* w_o  = (const float*)d_in[13];
    const float* b_o  = (const float*)d_in[14];
    float* out = (float*)d_out;

    static cudaStream_t s2 = nullptr;
    static cudaEvent_t evF = nullptr, evJ = nullptr;
    if (s2 == nullptr) {
        cudaStreamCreateWithFlags(&s2, cudaStreamNonBlocking);
        cudaEventCreateWithFlags(&evF, cudaEventDisableTiming);
        cudaEventCreateWithFlags(&evJ, cudaEventDisableTiming);
    }

    // main stream: setup -> fork pair_bias onto s2; ln+qkvg run concurrently
    setup_kernel<<<1, 256>>>(g_z, b_z, w_z);
    cudaEventRecord(evF, 0);
    cudaStreamWaitEvent(s2, evF, 0);
    pair_bias_kernel<<<dim3(N_TOK / 64, N_TOK), 256, 0, s2>>>(z, mask);
    cudaEventRecord(evJ, s2);

    ln_a_kernel<<<N_TOK, 256>>>(a, g_a, b_a);
    qkvg_proj_kernel<<<dim3(HDM / 64, N_TOK / 64, 4), 256>>>(w_q, w_k, w_v, w_g, b_g);

    cudaStreamWaitEvent(0, evJ, 0);   // join: flash needs pb + qkvg
    flash_kernel<<<dim3(N_TOK / 64, NH, KSPLIT), 256>>>();
    combine_kernel<<<(NH * N_TOK * HD) / 256, 256>>>();

    out_proj_kernel<<<dim3(CQ / 64, N_TOK / 32), 256>>>(w_o, b_o, out);
}